// round 11
// baseline (speedup 1.0000x reference)
#include <cuda_runtime.h>
#include <cuda_bf16.h>
#include <cstdint>

#define B_  8
#define N_  1024
#define C_  768
#define H_  12
#define HD_ 64
#define BH_ (B_*H_)          // 96
#define M_  (B_*N_)          // 8192
constexpr float SCALE = 0.125f;  // 64^-0.5

// ---- scratch ----
__device__ float g_q[B_*H_*N_*HD_];    // [b][h][n][d]
__device__ float g_k[B_*H_*N_*HD_];    // [b][h][n][d]
__device__ float g_v[B_*H_*HD_*N_];    // [b][h][d][n]  (transposed!)
__device__ float g_ctx[B_*N_*C_];      // [b][n][c]

// ---- helpers ----
__device__ __forceinline__ uint32_t f2tf(float f) {
    uint32_t u; asm("cvt.rna.tf32.f32 %0, %1;" : "=r"(u) : "f"(f)); return u;
}
__device__ __forceinline__ void ldsm4(uint32_t& r0, uint32_t& r1, uint32_t& r2, uint32_t& r3,
                                      const uint32_t* p) {
    uint32_t a = (uint32_t)__cvta_generic_to_shared(p);
    asm volatile("ldmatrix.sync.aligned.m8n8.x4.shared.b16 {%0,%1,%2,%3}, [%4];"
                 : "=r"(r0), "=r"(r1), "=r"(r2), "=r"(r3) : "r"(a));
}
__device__ __forceinline__ void mma8(float* c, const uint32_t* a, const uint32_t* b) {
    asm volatile("mma.sync.aligned.m16n8k8.row.col.f32.tf32.tf32.f32 "
                 "{%0,%1,%2,%3},{%4,%5,%6,%7},{%8,%9},{%0,%1,%2,%3};"
                 : "+f"(c[0]), "+f"(c[1]), "+f"(c[2]), "+f"(c[3])
                 : "r"(a[0]), "r"(a[1]), "r"(a[2]), "r"(a[3]), "r"(b[0]), "r"(b[1]));
}

// swizzled word index: K=32-wide rows (A tiles in GEMM)
#define AIDX(m,k) ((m)*32 + (((((k)>>2) ^ ((m)&7)))<<2) + ((k)&3))
// swizzled word index: 64-wide rows (attention tiles)
#define SIDX(r,c) ((r)*64 + (((((c)>>2) ^ ((r)&7)))<<2) + ((c)&3))
// quad-interleaved swizzled B tile: kf in 0..31 (k within tile), n in 0..127
// word = (n>>2)*128 + ((kf ^ ((n>>2)&7))<<2) + (n&3)
#define BQIDX(kf,n) (((n)>>2)*128 + ((((kf) ^ (((n)>>2)&7)))<<2) + ((n)&3))

// ============================================================
// Kernel 1: QKV GEMM (tf32 MMA) y = x @ w_qkv -> g_q/g_k/g_v
// (round-4 verbatim except B smem layout: BQIDX, 2-way banks)
// ============================================================
__global__ __launch_bounds__(256, 2) void qkv_gemm(const float* __restrict__ x,
                                                   const float* __restrict__ w) {
    __shared__ uint32_t As[128 * 32];
    __shared__ uint32_t Bs[32 * 128];
    const int tid = threadIdx.x, lane = tid & 31, warp = tid >> 5;
    const int wm = warp >> 1, wn = warp & 1;

    float acc[2][8][4];
#pragma unroll
    for (int i = 0; i < 2; i++)
#pragma unroll
        for (int j = 0; j < 8; j++)
#pragma unroll
            for (int r = 0; r < 4; r++) acc[i][j][r] = 0.f;

    const int am = tid >> 1, ak = (tid & 1) * 16;
    const float* ap = x + (size_t)(blockIdx.y * 128 + am) * 768 + ak;
    const int bk = (tid >> 5) * 4, bn = (tid & 31) * 4;
    const int bq = tid & 31;                 // = bn>>2
    const float* bp = w + (size_t)bk * 2304 + blockIdx.x * 128 + bn;

    // per-lane constants for B fragment addressing
    const int kq = lane & 3;                 // k within 4
    const int aq = lane >> 2;                // n sub-offset 0..7
    const int hq = lane >> 4;                // = aq>>2

    for (int kt = 0; kt < 768; kt += 32) {
#pragma unroll
        for (int u = 0; u < 4; u++) {
            float4 v = *(const float4*)(ap + kt + u * 4);
            uint4 t = make_uint4(f2tf(v.x), f2tf(v.y), f2tf(v.z), f2tf(v.w));
            *(uint4*)&As[AIDX(am, ak + u * 4)] = t;
        }
#pragma unroll
        for (int u = 0; u < 4; u++) {
            float4 v = *(const float4*)(bp + (size_t)(kt + u) * 2304);
            uint4 t = make_uint4(f2tf(v.x), f2tf(v.y), f2tf(v.z), f2tf(v.w));
            *(uint4*)&Bs[bq * 128 + (((bk + u) ^ (bq & 7)) << 2)] = t;
        }
        __syncthreads();
#pragma unroll
        for (int ks = 0; ks < 4; ks++) {
            uint32_t a[2][4], b[8][2];
#pragma unroll
            for (int i = 0; i < 2; i++) {
                const int row = wm * 32 + i * 16 + ((lane >> 3) & 1) * 8 + (lane & 7);
                const int grp = ks * 2 + (lane >> 4);
                ldsm4(a[i][0], a[i][1], a[i][2], a[i][3],
                      &As[row * 32 + ((grp ^ (row & 7)) << 2)]);
            }
#pragma unroll
            for (int j = 0; j < 8; j++) {
                const int nq = wn * 16 + 2 * j + hq;
                const int m7 = nq & 7;
                b[j][0] = Bs[nq * 128 + (((ks * 8 + kq) ^ m7) << 2) + (aq & 3)];
                b[j][1] = Bs[nq * 128 + (((ks * 8 + 4 + kq) ^ m7) << 2) + (aq & 3)];
            }
#pragma unroll
            for (int i = 0; i < 2; i++)
#pragma unroll
                for (int j = 0; j < 8; j++) mma8(acc[i][j], a[i], b[j]);
        }
        __syncthreads();
    }

    // epilogue: warp covers exactly one head section (64 cols)  [round-4 verbatim]
    const int n0 = blockIdx.x * 128 + wn * 64;
    const int sec = n0 / 768;
    const int h = (n0 - sec * 768) >> 6;
#pragma unroll
    for (int i = 0; i < 2; i++)
#pragma unroll
        for (int li = 0; li < 2; li++) {
            const int m = blockIdx.y * 128 + wm * 32 + i * 16 + li * 8 + (lane >> 2);
            const int b = m >> 10, tok = m & 1023;
            if (sec < 2) {
                float* base = (sec == 0 ? g_q : g_k) +
                              ((size_t)(b * H_ + h) * 1024 + tok) * 64 + 2 * (lane & 3);
#pragma unroll
                for (int j = 0; j < 8; j++)
                    *(float2*)(base + j * 8) = make_float2(acc[i][j][li * 2], acc[i][j][li * 2 + 1]);
            } else {
                float* base = g_v + (size_t)(b * H_ + h) * 65536 + tok;
#pragma unroll
                for (int j = 0; j < 8; j++) {
                    const int d = j * 8 + 2 * (lane & 3);
                    base[(size_t)d * 1024]       = acc[i][j][li * 2];
                    base[(size_t)(d + 1) * 1024] = acc[i][j][li * 2 + 1];
                }
            }
        }
}

// ============================================================
// Kernel 2: flash attention (round-4 VERBATIM)
// ============================================================
__global__ __launch_bounds__(128) void attn_kernel() {
    __shared__ uint32_t Qs[64 * 64];
    __shared__ uint32_t Ks[64 * 64];   // K tile, then reused for P
    __shared__ uint32_t Vs[64 * 64];   // V^T tile [d][tok]
    const int tid = threadIdx.x, lane = tid & 31, warp = tid >> 5;
    const int q0 = blockIdx.x * 64, bh = blockIdx.y;

    // load Q (scaled, tf32)
    {
        const int row = tid >> 1, half = tid & 1;
        const float* qp = g_q + ((size_t)bh * 1024 + q0 + row) * 64 + half * 32;
#pragma unroll
        for (int u = 0; u < 8; u++) {
            float4 v = *(const float4*)(qp + u * 4);
            uint4 t = make_uint4(f2tf(v.x * SCALE), f2tf(v.y * SCALE),
                                 f2tf(v.z * SCALE), f2tf(v.w * SCALE));
            *(uint4*)&Qs[SIDX(row, half * 32 + u * 4)] = t;
        }
    }

    float o[8][4];
#pragma unroll
    for (int j = 0; j < 8; j++)
#pragma unroll
        for (int r = 0; r < 4; r++) o[j][r] = 0.f;
    float mA = -1e30f, mB = -1e30f, lA = 0.f, lB = 0.f;

    const float* kbase = g_k + (size_t)bh * 65536;
    const float* vbase = g_v + (size_t)bh * 65536;

    for (int kt = 0; kt < 1024; kt += 64) {
        {   // load K tile [tok][d] and V^T tile [d][tok]
            const int row = tid >> 1, half = tid & 1;
            const float* kp = kbase + (size_t)(kt + row) * 64 + half * 32;
            const float* vp = vbase + (size_t)row * 1024 + kt + half * 32;
#pragma unroll
            for (int u = 0; u < 8; u++) {
                float4 kv = *(const float4*)(kp + u * 4);
                *(uint4*)&Ks[SIDX(row, half * 32 + u * 4)] =
                    make_uint4(f2tf(kv.x), f2tf(kv.y), f2tf(kv.z), f2tf(kv.w));
                float4 vv = *(const float4*)(vp + u * 4);
                *(uint4*)&Vs[SIDX(row, half * 32 + u * 4)] =
                    make_uint4(f2tf(vv.x), f2tf(vv.y), f2tf(vv.z), f2tf(vv.w));
            }
        }
        __syncthreads();

        // S = Q K^T
        float s[8][4];
#pragma unroll
        for (int j = 0; j < 8; j++)
#pragma unroll
            for (int r = 0; r < 4; r++) s[j][r] = 0.f;
#pragma unroll
        for (int ks = 0; ks < 8; ks++) {
            uint32_t a[4], b[8][2];
            {
                const int row = warp * 16 + ((lane >> 3) & 1) * 8 + (lane & 7);
                const int grp = ks * 2 + (lane >> 4);
                ldsm4(a[0], a[1], a[2], a[3], &Qs[row * 64 + ((grp ^ (row & 7)) << 2)]);
            }
#pragma unroll
            for (int jp = 0; jp < 4; jp++) {
                const int row = jp * 16 + ((lane >> 4) & 1) * 8 + (lane & 7);
                const int grp = ks * 2 + ((lane >> 3) & 1);
                ldsm4(b[2 * jp][0], b[2 * jp][1], b[2 * jp + 1][0], b[2 * jp + 1][1],
                      &Ks[row * 64 + ((grp ^ (row & 7)) << 2)]);
            }
#pragma unroll
            for (int j = 0; j < 8; j++) mma8(s[j], a, b[j]);
        }
        __syncthreads();   // everyone done reading K before P overwrite

        // online softmax: rows ra = warp*16+(lane>>2), rb = ra+8
        float mxa = -1e30f, mxb = -1e30f;
#pragma unroll
        for (int j = 0; j < 8; j++) {
            mxa = fmaxf(mxa, fmaxf(s[j][0], s[j][1]));
            mxb = fmaxf(mxb, fmaxf(s[j][2], s[j][3]));
        }
#pragma unroll
        for (int off = 1; off <= 2; off <<= 1) {
            mxa = fmaxf(mxa, __shfl_xor_sync(0xffffffffu, mxa, off));
            mxb = fmaxf(mxb, __shfl_xor_sync(0xffffffffu, mxb, off));
        }
        const float mnA = fmaxf(mA, mxa), mnB = fmaxf(mB, mxb);
        const float facA = __expf(mA - mnA), facB = __expf(mB - mnB);
        mA = mnA; mB = mnB;
        float sa = 0.f, sb = 0.f;
#pragma unroll
        for (int j = 0; j < 8; j++) {
            s[j][0] = __expf(s[j][0] - mA); s[j][1] = __expf(s[j][1] - mA);
            s[j][2] = __expf(s[j][2] - mB); s[j][3] = __expf(s[j][3] - mB);
            sa += s[j][0] + s[j][1]; sb += s[j][2] + s[j][3];
        }
#pragma unroll
        for (int off = 1; off <= 2; off <<= 1) {
            sa += __shfl_xor_sync(0xffffffffu, sa, off);
            sb += __shfl_xor_sync(0xffffffffu, sb, off);
        }
        lA = lA * facA + sa; lB = lB * facB + sb;
#pragma unroll
        for (int j = 0; j < 8; j++) {
            o[j][0] *= facA; o[j][1] *= facA; o[j][2] *= facB; o[j][3] *= facB;
        }

        // store P (tf32) into Ks (own rows only)
        {
            const int ra = warp * 16 + (lane >> 2), rb = ra + 8;
#pragma unroll
            for (int j = 0; j < 8; j++) {
                const int c0 = j * 8 + 2 * (lane & 3);
                *(uint2*)&Ks[SIDX(ra, c0)] = make_uint2(f2tf(s[j][0]), f2tf(s[j][1]));
                *(uint2*)&Ks[SIDX(rb, c0)] = make_uint2(f2tf(s[j][2]), f2tf(s[j][3]));
            }
        }
        __syncwarp();

        // O += P V   (A = P from Ks own rows, B = V^T from Vs)
#pragma unroll
        for (int ks = 0; ks < 8; ks++) {
            uint32_t a[4], b[8][2];
            {
                const int row = warp * 16 + ((lane >> 3) & 1) * 8 + (lane & 7);
                const int grp = ks * 2 + (lane >> 4);
                ldsm4(a[0], a[1], a[2], a[3], &Ks[row * 64 + ((grp ^ (row & 7)) << 2)]);
            }
#pragma unroll
            for (int jp = 0; jp < 4; jp++) {
                const int row = jp * 16 + ((lane >> 4) & 1) * 8 + (lane & 7);
                const int grp = ks * 2 + ((lane >> 3) & 1);
                ldsm4(b[2 * jp][0], b[2 * jp][1], b[2 * jp + 1][0], b[2 * jp + 1][1],
                      &Vs[row * 64 + ((grp ^ (row & 7)) << 2)]);
            }
#pragma unroll
            for (int j = 0; j < 8; j++) mma8(o[j], a, b[j]);
        }
        __syncthreads();   // done reading Ks(P)/Vs before next tile load
    }

    // normalize + write ctx
    const int b = bh / H_, h = bh - b * H_;
    const int ra = warp * 16 + (lane >> 2);
    const float invA = 1.f / lA, invB = 1.f / lB;
    float* pa = g_ctx + ((size_t)(b * 1024) + q0 + ra) * 768 + h * 64 + 2 * (lane & 3);
    float* pb = g_ctx + ((size_t)(b * 1024) + q0 + ra + 8) * 768 + h * 64 + 2 * (lane & 3);
#pragma unroll
    for (int j = 0; j < 8; j++) {
        *(float2*)(pa + j * 8) = make_float2(o[j][0] * invA, o[j][1] * invA);
        *(float2*)(pb + j * 8) = make_float2(o[j][2] * invB, o[j][3] * invB);
    }
}

// ============================================================
// Kernel 3: out projection (tf32 MMA) out = ctx @ w_out + b_out
// (round-4 verbatim except B smem layout: BQIDX)
// ============================================================
__global__ __launch_bounds__(256, 2) void out_gemm(const float* __restrict__ w,
                                                   const float* __restrict__ bias,
                                                   float* __restrict__ out) {
    __shared__ uint32_t As[128 * 32];
    __shared__ uint32_t Bs[32 * 128];
    const int tid = threadIdx.x, lane = tid & 31, warp = tid >> 5;
    const int wm = warp >> 1, wn = warp & 1;

    float acc[2][8][4];
#pragma unroll
    for (int i = 0; i < 2; i++)
#pragma unroll
        for (int j = 0; j < 8; j++)
#pragma unroll
            for (int r = 0; r < 4; r++) acc[i][j][r] = 0.f;

    const int am = tid >> 1, ak = (tid & 1) * 16;
    const float* ap = g_ctx + (size_t)(blockIdx.y * 128 + am) * 768 + ak;
    const int bk = (tid >> 5) * 4, bn = (tid & 31) * 4;
    const int bq = tid & 31;
    const float* bp = w + (size_t)bk * 768 + blockIdx.x * 128 + bn;

    const int kq = lane & 3;
    const int aq = lane >> 2;
    const int hq = lane >> 4;

    for (int kt = 0; kt < 768; kt += 32) {
#pragma unroll
        for (int u = 0; u < 4; u++) {
            float4 v = *(const float4*)(ap + kt + u * 4);
            uint4 t = make_uint4(f2tf(v.x), f2tf(v.y), f2tf(v.z), f2tf(v.w));
            *(uint4*)&As[AIDX(am, ak + u * 4)] = t;
        }
#pragma unroll
        for (int u = 0; u < 4; u++) {
            float4 v = *(const float4*)(bp + (size_t)(kt + u) * 768);
            uint4 t = make_uint4(f2tf(v.x), f2tf(v.y), f2tf(v.z), f2tf(v.w));
            *(uint4*)&Bs[bq * 128 + (((bk + u) ^ (bq & 7)) << 2)] = t;
        }
        __syncthreads();
#pragma unroll
        for (int ks = 0; ks < 4; ks++) {
            uint32_t a[2][4], b[8][2];
#pragma unroll
            for (int i = 0; i < 2; i++) {
                const int row = wm * 32 + i * 16 + ((lane >> 3) & 1) * 8 + (lane & 7);
                const int grp = ks * 2 + (lane >> 4);
                ldsm4(a[i][0], a[i][1], a[i][2], a[i][3],
                      &As[row * 32 + ((grp ^ (row & 7)) << 2)]);
            }
#pragma unroll
            for (int j = 0; j < 8; j++) {
                const int nq = wn * 16 + 2 * j + hq;
                const int m7 = nq & 7;
                b[j][0] = Bs[nq * 128 + (((ks * 8 + kq) ^ m7) << 2) + (aq & 3)];
                b[j][1] = Bs[nq * 128 + (((ks * 8 + 4 + kq) ^ m7) << 2) + (aq & 3)];
            }
#pragma unroll
            for (int i = 0; i < 2; i++)
#pragma unroll
                for (int j = 0; j < 8; j++) mma8(acc[i][j], a[i], b[j]);
        }
        __syncthreads();
    }

    const int n0 = blockIdx.x * 128 + wn * 64 + 2 * (lane & 3);
#pragma unroll
    for (int i = 0; i < 2; i++)
#pragma unroll
        for (int li = 0; li < 2; li++) {
            const int m = blockIdx.y * 128 + wm * 32 + i * 16 + li * 8 + (lane >> 2);
            float* op = out + (size_t)m * 768 + n0;
#pragma unroll
            for (int j = 0; j < 8; j++) {
                float2 bb = *(const float2*)(bias + n0 + j * 8);
                *(float2*)(op + j * 8) =
                    make_float2(acc[i][j][li * 2] + bb.x, acc[i][j][li * 2 + 1] + bb.y);
            }
        }
}

// ============================================================
extern "C" void kernel_launch(void* const* d_in, const int* in_sizes, int n_in,
                              void* d_out, int out_size) {
    const float* x     = (const float*)d_in[0];
    const float* w_qkv = (const float*)d_in[1];
    const float* w_out = (const float*)d_in[2];
    const float* b_out = (const float*)d_in[3];
    float* out = (float*)d_out;

    qkv_gemm<<<dim3(2304 / 128, M_ / 128), 256>>>(x, w_qkv);
    attn_kernel<<<dim3(N_ / 64, BH_), 128>>>();
    out_gemm<<<dim3(768 / 128, M_ / 128), 256>>>(w_out, b_out, out);
}

// round 12
// speedup vs baseline: 1.0784x; 1.0784x over previous
#include <cuda_runtime.h>
#include <cuda_bf16.h>
#include <cstdint>

#define B_  8
#define N_  1024
#define C_  768
#define H_  12
#define HD_ 64
#define BH_ (B_*H_)          // 96
#define M_  (B_*N_)          // 8192
constexpr float SCALE = 0.125f;  // 64^-0.5

// ---- scratch ----
__device__ float g_q[B_*H_*N_*HD_];     // [b][h][n][d]   tf32-rounded, pre-scaled
__device__ float g_k[B_*H_*N_*HD_];     // [b][h][n][d]   tf32-rounded
__device__ float g_v[B_*H_*HD_*N_];     // [b][h][d][n]   transposed, tf32-rounded
__device__ float g_ctx[B_*N_*C_];       // [b][n][c]      tf32-rounded
__device__ float g_xa[M_*C_];           // x tf32-rounded
__device__ float g_wqkvT[3*C_*C_];      // w_qkv^T [n][k] tf32-rounded
__device__ float g_woutT[C_*C_];        // w_out^T [n][k] tf32-rounded

// ---- helpers ----
__device__ __forceinline__ uint32_t f2tf(float f) {
    uint32_t u; asm("cvt.rna.tf32.f32 %0, %1;" : "=r"(u) : "f"(f)); return u;
}
__device__ __forceinline__ void ldsm4(uint32_t& r0, uint32_t& r1, uint32_t& r2, uint32_t& r3,
                                      const uint32_t* p) {
    uint32_t a = (uint32_t)__cvta_generic_to_shared(p);
    asm volatile("ldmatrix.sync.aligned.m8n8.x4.shared.b16 {%0,%1,%2,%3}, [%4];"
                 : "=r"(r0), "=r"(r1), "=r"(r2), "=r"(r3) : "r"(a));
}
__device__ __forceinline__ void mma8(float* c, const uint32_t* a, const uint32_t* b) {
    asm volatile("mma.sync.aligned.m16n8k8.row.col.f32.tf32.tf32.f32 "
                 "{%0,%1,%2,%3},{%4,%5,%6,%7},{%8,%9},{%0,%1,%2,%3};"
                 : "+f"(c[0]), "+f"(c[1]), "+f"(c[2]), "+f"(c[3])
                 : "r"(a[0]), "r"(a[1]), "r"(a[2]), "r"(a[3]), "r"(b[0]), "r"(b[1]));
}
__device__ __forceinline__ void cpasync16(uint32_t* dst, const void* src) {
    uint32_t d = (uint32_t)__cvta_generic_to_shared(dst);
    asm volatile("cp.async.ca.shared.global [%0], [%1], 16;" :: "r"(d), "l"(src));
}
#define CP_COMMIT asm volatile("cp.async.commit_group;")
#define CP_WAIT0  asm volatile("cp.async.wait_group 0;")

// swizzled word index, 32-word rows (GEMM tiles); kg = 16-byte group 0..7
#define AIDX(m,kg) ((m)*32 + (((kg) ^ ((m)&7))<<2))
// swizzled word index, 64-word rows (attention tiles)
#define SIDX(r,c) ((r)*64 + (((((c)>>2) ^ ((r)&7)))<<2) + ((c)&3))

// ============================================================
// Prepass: tf32-round x; tf32-round + transpose weights.
// DESTINATIONS ARE DEVICE SYMBOLS REFERENCED IN-KERNEL — never
// passed from host (that was the rounds-5/6/9 bug).
// ============================================================
__global__ __launch_bounds__(256) void cvt_x_kernel(const float* __restrict__ x) {
    const size_t i = ((size_t)blockIdx.x * 256 + threadIdx.x) * 4;
    float4 v = *(const float4*)(x + i);
    *(uint4*)(g_xa + i) = make_uint4(f2tf(v.x), f2tf(v.y), f2tf(v.z), f2tf(v.w));
}

// src [768][COLS] row-major -> dst [COLS][768], tf32-rounded
template <int COLS>
__global__ __launch_bounds__(256) void cvt_transpose_k(const float* __restrict__ src) {
    float* dst = (COLS == 2304) ? g_wqkvT : g_woutT;
    __shared__ float tile[32][33];
    const int c0 = blockIdx.x * 32, r0 = blockIdx.y * 32;
    const int tx = threadIdx.x, ty = threadIdx.y;
#pragma unroll
    for (int u = 0; u < 4; u++)
        tile[ty + u * 8][tx] = src[(size_t)(r0 + ty + u * 8) * COLS + c0 + tx];
    __syncthreads();
#pragma unroll
    for (int u = 0; u < 4; u++) {
        const int c = c0 + ty + u * 8, r = r0 + tx;
        ((uint32_t*)dst)[(size_t)c * 768 + r] = f2tf(tile[tx][ty + u * 8]);
    }
}

// ============================================================
// GEMM core: 128x128x32 tiles, double-buffered cp.async, all-ldmatrix.
// A [m][k] k-major (pre-rounded), BT [n][k] k-major (pre-rounded), K=768.
// ============================================================
__device__ __forceinline__ void gemm_fill(uint32_t* As, uint32_t* Bs,
                                          const float* A, const float* BT,
                                          int by128, int bx128, int kt, int tid) {
#pragma unroll
    for (int u = 0; u < 4; u++) {
        const int g = tid + u * 256;
        const int row = g >> 3, kg = g & 7;
        cpasync16(&As[AIDX(row, kg)], A + (size_t)(by128 + row) * 768 + kt + kg * 4);
        cpasync16(&Bs[AIDX(row, kg)], BT + (size_t)(bx128 + row) * 768 + kt + kg * 4);
    }
}

__device__ __forceinline__ void gemm_core(const float* A, const float* BT,
                                          float acc[2][8][4]) {
    extern __shared__ uint32_t smem[];
    uint32_t* As = smem;            // [2][128*32]
    uint32_t* Bs = smem + 8192;     // [2][128*32]
    const int tid = threadIdx.x, lane = tid & 31, warp = tid >> 5;
    const int wm = warp >> 1, wn = warp & 1;
    const int by128 = blockIdx.y * 128, bx128 = blockIdx.x * 128;

    gemm_fill(As, Bs, A, BT, by128, bx128, 0, tid);
    CP_COMMIT;

    for (int t = 0; t < 24; t++) {
        const int cur = t & 1;
        CP_WAIT0;
        __syncthreads();
        if (t < 23) {
            gemm_fill(As + (cur ^ 1) * 4096, Bs + (cur ^ 1) * 4096,
                      A, BT, by128, bx128, (t + 1) * 32, tid);
            CP_COMMIT;
        }
        const uint32_t* Ab = As + cur * 4096;
        const uint32_t* Bb = Bs + cur * 4096;
#pragma unroll
        for (int ks = 0; ks < 4; ks++) {
            uint32_t a[2][4], b[8][2];
            const int grp = ks * 2 + (lane >> 4);
#pragma unroll
            for (int i = 0; i < 2; i++) {
                const int row = wm * 32 + i * 16 + ((lane >> 3) & 1) * 8 + (lane & 7);
                ldsm4(a[i][0], a[i][1], a[i][2], a[i][3], &Ab[AIDX(row, grp)]);
            }
#pragma unroll
            for (int jp = 0; jp < 4; jp++) {
                const int row = wn * 64 + jp * 16 + ((lane >> 3) & 1) * 8 + (lane & 7);
                ldsm4(b[2 * jp][0], b[2 * jp + 1][0], b[2 * jp][1], b[2 * jp + 1][1],
                      &Bb[AIDX(row, grp)]);
            }
#pragma unroll
            for (int i = 0; i < 2; i++)
#pragma unroll
                for (int j = 0; j < 8; j++) mma8(acc[i][j], a[i], b[j]);
        }
        __syncthreads();
    }
}

// ============================================================
// Kernel 1: QKV GEMM -> g_q (scaled) / g_k / g_v (transposed), tf32-rounded
// ============================================================
__global__ __launch_bounds__(256, 2) void qkv_gemm() {
    float acc[2][8][4];
#pragma unroll
    for (int i = 0; i < 2; i++)
#pragma unroll
        for (int j = 0; j < 8; j++)
#pragma unroll
            for (int r = 0; r < 4; r++) acc[i][j][r] = 0.f;

    gemm_core(g_xa, g_wqkvT, acc);

    const int tid = threadIdx.x, lane = tid & 31, warp = tid >> 5;
    const int wm = warp >> 1, wn = warp & 1;
    const int n0 = blockIdx.x * 128 + wn * 64;
    const int sec = n0 / 768;
    const int h = (n0 - sec * 768) >> 6;
#pragma unroll
    for (int i = 0; i < 2; i++)
#pragma unroll
        for (int li = 0; li < 2; li++) {
            const int m = blockIdx.y * 128 + wm * 32 + i * 16 + li * 8 + (lane >> 2);
            const int b = m >> 10, tok = m & 1023;
            if (sec == 0) {
                uint32_t* base = (uint32_t*)g_q +
                    ((size_t)(b * H_ + h) * 1024 + tok) * 64 + 2 * (lane & 3);
#pragma unroll
                for (int j = 0; j < 8; j++)
                    *(uint2*)(base + j * 8) = make_uint2(f2tf(acc[i][j][li * 2] * SCALE),
                                                         f2tf(acc[i][j][li * 2 + 1] * SCALE));
            } else if (sec == 1) {
                uint32_t* base = (uint32_t*)g_k +
                    ((size_t)(b * H_ + h) * 1024 + tok) * 64 + 2 * (lane & 3);
#pragma unroll
                for (int j = 0; j < 8; j++)
                    *(uint2*)(base + j * 8) = make_uint2(f2tf(acc[i][j][li * 2]),
                                                         f2tf(acc[i][j][li * 2 + 1]));
            } else {
                uint32_t* base = (uint32_t*)g_v + (size_t)(b * H_ + h) * 65536 + tok;
#pragma unroll
                for (int j = 0; j < 8; j++) {
                    const int d = j * 8 + 2 * (lane & 3);
                    base[(size_t)d * 1024]       = f2tf(acc[i][j][li * 2]);
                    base[(size_t)(d + 1) * 1024] = f2tf(acc[i][j][li * 2 + 1]);
                }
            }
        }
}

// ============================================================
// Kernel 2: flash attention, tf32 MMA, cp.async double-buffered K/V.
// 64 q-rows per CTA, 4 warps. smem: Qs 16K + Ks 2x16K + Vs 2x16K = 80KB
// ============================================================
__device__ __forceinline__ void attn_loadKV(uint32_t* Ks, uint32_t* Vs,
                                            const float* kbase, const float* vbase,
                                            int kt, int tid) {
#pragma unroll
    for (int u = 0; u < 8; u++) {
        const int g = tid + u * 128;
        const int row = g >> 4, kg = g & 15;
        cpasync16(&Ks[SIDX(row, kg * 4)], kbase + (size_t)(kt + row) * 64 + kg * 4);
        cpasync16(&Vs[SIDX(row, kg * 4)], vbase + (size_t)row * 1024 + kt + kg * 4);
    }
}

__global__ __launch_bounds__(128) void attn_kernel() {
    extern __shared__ uint32_t smem[];
    uint32_t* Qs = smem;             // 64*64
    uint32_t* Ks = smem + 4096;      // [2][64*64]  (K tile; P reuses current buffer)
    uint32_t* Vs = smem + 12288;     // [2][64*64]
    const int tid = threadIdx.x, lane = tid & 31, warp = tid >> 5;
    const int q0 = blockIdx.x * 64, bh = blockIdx.y;
    const float* qbase = g_q + (size_t)bh * 65536 + (size_t)q0 * 64;
    const float* kbase = g_k + (size_t)bh * 65536;
    const float* vbase = g_v + (size_t)bh * 65536;

    // Q tile (already tf32 + scaled) via cp.async
#pragma unroll
    for (int u = 0; u < 8; u++) {
        const int g = tid + u * 128;
        const int row = g >> 4, kg = g & 15;
        cpasync16(&Qs[SIDX(row, kg * 4)], qbase + (size_t)row * 64 + kg * 4);
    }
    attn_loadKV(Ks, Vs, kbase, vbase, 0, tid);
    CP_COMMIT;

    float o[8][4];
#pragma unroll
    for (int j = 0; j < 8; j++)
#pragma unroll
        for (int r = 0; r < 4; r++) o[j][r] = 0.f;
    float mA = -1e30f, mB = -1e30f, lA = 0.f, lB = 0.f;

    for (int t = 0; t < 16; t++) {
        const int cur = t & 1;
        CP_WAIT0;
        __syncthreads();
        if (t < 15) {
            attn_loadKV(Ks + (cur ^ 1) * 4096, Vs + (cur ^ 1) * 4096,
                        kbase, vbase, (t + 1) * 64, tid);
            CP_COMMIT;
        }
        uint32_t* Kb = Ks + cur * 4096;
        const uint32_t* Vb = Vs + cur * 4096;

        // S = Q K^T
        float s[8][4];
#pragma unroll
        for (int j = 0; j < 8; j++)
#pragma unroll
            for (int r = 0; r < 4; r++) s[j][r] = 0.f;
#pragma unroll
        for (int ks = 0; ks < 8; ks++) {
            uint32_t a[4], b[8][2];
            {
                const int row = warp * 16 + ((lane >> 3) & 1) * 8 + (lane & 7);
                const int grp = ks * 2 + (lane >> 4);
                ldsm4(a[0], a[1], a[2], a[3], &Qs[row * 64 + ((grp ^ (row & 7)) << 2)]);
            }
#pragma unroll
            for (int jp = 0; jp < 4; jp++) {
                const int row = jp * 16 + ((lane >> 3) & 1) * 8 + (lane & 7);
                const int grp = ks * 2 + (lane >> 4);
                ldsm4(b[2 * jp][0], b[2 * jp + 1][0], b[2 * jp][1], b[2 * jp + 1][1],
                      &Kb[row * 64 + ((grp ^ (row & 7)) << 2)]);
            }
#pragma unroll
            for (int j = 0; j < 8; j++) mma8(s[j], a, b[j]);
        }
        __syncthreads();   // all warps done reading K before P overwrite

        // online softmax (rows ra=warp*16+(lane>>2), rb=ra+8)
        float mxa = -1e30f, mxb = -1e30f;
#pragma unroll
        for (int j = 0; j < 8; j++) {
            mxa = fmaxf(mxa, fmaxf(s[j][0], s[j][1]));
            mxb = fmaxf(mxb, fmaxf(s[j][2], s[j][3]));
        }
#pragma unroll
        for (int off = 1; off <= 2; off <<= 1) {
            mxa = fmaxf(mxa, __shfl_xor_sync(0xffffffffu, mxa, off));
            mxb = fmaxf(mxb, __shfl_xor_sync(0xffffffffu, mxb, off));
        }
        const float mnA = fmaxf(mA, mxa), mnB = fmaxf(mB, mxb);
        const float facA = __expf(mA - mnA), facB = __expf(mB - mnB);
        mA = mnA; mB = mnB;
        float sa = 0.f, sb = 0.f;
#pragma unroll
        for (int j = 0; j < 8; j++) {
            s[j][0] = __expf(s[j][0] - mA); s[j][1] = __expf(s[j][1] - mA);
            s[j][2] = __expf(s[j][2] - mB); s[j][3] = __expf(s[j][3] - mB);
            sa += s[j][0] + s[j][1]; sb += s[j][2] + s[j][3];
        }
#pragma unroll
        for (int off = 1; off <= 2; off <<= 1) {
            sa += __shfl_xor_sync(0xffffffffu, sa, off);
            sb += __shfl_xor_sync(0xffffffffu, sb, off);
        }
        lA = lA * facA + sa; lB = lB * facB + sb;
#pragma unroll
        for (int j = 0; j < 8; j++) {
            o[j][0] *= facA; o[j][1] *= facA; o[j][2] *= facB; o[j][3] *= facB;
        }

        // store P (tf32) into current K buffer (own rows only)
        {
            const int ra = warp * 16 + (lane >> 2), rb = ra + 8;
#pragma unroll
            for (int j = 0; j < 8; j++) {
                const int c0 = j * 8 + 2 * (lane & 3);
                *(uint2*)&Kb[SIDX(ra, c0)] = make_uint2(f2tf(s[j][0]), f2tf(s[j][1]));
                *(uint2*)&Kb[SIDX(rb, c0)] = make_uint2(f2tf(s[j][2]), f2tf(s[j][3]));
            }
        }
        __syncwarp();

        // O += P V  (A = own P rows, B = V^T)
#pragma unroll
        for (int ks = 0; ks < 8; ks++) {
            uint32_t a[4], b[8][2];
            {
                const int row = warp * 16 + ((lane >> 3) & 1) * 8 + (lane & 7);
                const int grp = ks * 2 + (lane >> 4);
                ldsm4(a[0], a[1], a[2], a[3], &Kb[row * 64 + ((grp ^ (row & 7)) << 2)]);
            }
#pragma unroll
            for (int jp = 0; jp < 4; jp++) {
                const int row = jp * 16 + ((lane >> 3) & 1) * 8 + (lane & 7);
                const int grp = ks * 2 + (lane >> 4);
                ldsm4(b[2 * jp][0], b[2 * jp + 1][0], b[2 * jp][1], b[2 * jp + 1][1],
                      &Vb[row * 64 + ((grp ^ (row & 7)) << 2)]);
            }
#pragma unroll
            for (int j = 0; j < 8; j++) mma8(o[j], a, b[j]);
        }
        // top-of-loop __syncthreads() orders these reads vs. next prefetch into this buffer
    }

    // normalize + write ctx (tf32-rounded for out_gemm)
    const int b = bh / H_, h = bh - b * H_;
    const int ra = warp * 16 + (lane >> 2);
    const float invA = 1.f / lA, invB = 1.f / lB;
    uint32_t* pa = (uint32_t*)g_ctx + ((size_t)(b * 1024) + q0 + ra) * 768 + h * 64 + 2 * (lane & 3);
    uint32_t* pb = (uint32_t*)g_ctx + ((size_t)(b * 1024) + q0 + ra + 8) * 768 + h * 64 + 2 * (lane & 3);
#pragma unroll
    for (int j = 0; j < 8; j++) {
        *(uint2*)(pa + j * 8) = make_uint2(f2tf(o[j][0] * invA), f2tf(o[j][1] * invA));
        *(uint2*)(pb + j * 8) = make_uint2(f2tf(o[j][2] * invB), f2tf(o[j][3] * invB));
    }
}

// ============================================================
// Kernel 3: out projection  out = ctx @ w_out + b_out
// ============================================================
__global__ __launch_bounds__(256, 2) void out_gemm(const float* __restrict__ bias,
                                                   float* __restrict__ out) {
    float acc[2][8][4];
#pragma unroll
    for (int i = 0; i < 2; i++)
#pragma unroll
        for (int j = 0; j < 8; j++)
#pragma unroll
            for (int r = 0; r < 4; r++) acc[i][j][r] = 0.f;

    gemm_core(g_ctx, g_woutT, acc);

    const int tid = threadIdx.x, lane = tid & 31, warp = tid >> 5;
    const int wm = warp >> 1, wn = warp & 1;
    const int n0 = blockIdx.x * 128 + wn * 64 + 2 * (lane & 3);
#pragma unroll
    for (int i = 0; i < 2; i++)
#pragma unroll
        for (int li = 0; li < 2; li++) {
            const int m = blockIdx.y * 128 + wm * 32 + i * 16 + li * 8 + (lane >> 2);
            float* op = out + (size_t)m * 768 + n0;
#pragma unroll
            for (int j = 0; j < 8; j++) {
                float2 bb = *(const float2*)(bias + n0 + j * 8);
                *(float2*)(op + j * 8) =
                    make_float2(acc[i][j][li * 2] + bb.x, acc[i][j][li * 2 + 1] + bb.y);
            }
        }
}

// ============================================================
extern "C" void kernel_launch(void* const* d_in, const int* in_sizes, int n_in,
                              void* d_out, int out_size) {
    const float* x     = (const float*)d_in[0];
    const float* w_qkv = (const float*)d_in[1];
    const float* w_out = (const float*)d_in[2];
    const float* b_out = (const float*)d_in[3];
    float* out = (float*)d_out;

    cudaFuncSetAttribute(qkv_gemm, cudaFuncAttributeMaxDynamicSharedMemorySize, 65536);
    cudaFuncSetAttribute(out_gemm, cudaFuncAttributeMaxDynamicSharedMemorySize, 65536);
    cudaFuncSetAttribute(attn_kernel, cudaFuncAttributeMaxDynamicSharedMemorySize, 81920);

    cvt_x_kernel<<<M_ * C_ / 1024, 256>>>(x);
    cvt_transpose_k<2304><<<dim3(2304 / 32, 768 / 32), dim3(32, 8)>>>(w_qkv);
    cvt_transpose_k<768><<<dim3(768 / 32, 768 / 32), dim3(32, 8)>>>(w_out);
    qkv_gemm<<<dim3(2304 / 128, M_ / 128), 256, 65536>>>();
    attn_kernel<<<dim3(N_ / 64, BH_), 128, 81920>>>();
    out_gemm<<<dim3(768 / 128, M_ / 128), 256, 65536>>>(b_out, out);
}

// round 13
// speedup vs baseline: 1.6069x; 1.4901x over previous
#include <cuda_runtime.h>
#include <cuda_bf16.h>
#include <cstdint>

#define B_  8
#define N_  1024
#define C_  768
#define H_  12
#define HD_ 64
#define BH_ (B_*H_)          // 96
#define M_  (B_*N_)          // 8192
constexpr float SCALE = 0.125f;  // 64^-0.5

// ---- scratch ----
__device__ float g_q[B_*H_*N_*HD_];     // [b][h][n][d]   tf32-rounded, pre-scaled
__device__ float g_k[B_*H_*N_*HD_];     // [b][h][n][d]   tf32-rounded
__device__ float g_v[B_*H_*HD_*N_];     // [b][h][d][n]   transposed, tf32-rounded
__device__ float g_ctx[B_*N_*C_];       // [b][n][c]      tf32-rounded
__device__ float g_xa[M_*C_];           // x tf32-rounded
__device__ float g_wqkvT[3*C_*C_];      // w_qkv^T [n][k] tf32-rounded
__device__ float g_woutT[C_*C_];        // w_out^T [n][k] tf32-rounded

// ---- helpers ----
__device__ __forceinline__ uint32_t f2tf(float f) {
    uint32_t u; asm("cvt.rna.tf32.f32 %0, %1;" : "=r"(u) : "f"(f)); return u;
}
__device__ __forceinline__ void ldsm4(uint32_t& r0, uint32_t& r1, uint32_t& r2, uint32_t& r3,
                                      const uint32_t* p) {
    uint32_t a = (uint32_t)__cvta_generic_to_shared(p);
    asm volatile("ldmatrix.sync.aligned.m8n8.x4.shared.b16 {%0,%1,%2,%3}, [%4];"
                 : "=r"(r0), "=r"(r1), "=r"(r2), "=r"(r3) : "r"(a));
}
__device__ __forceinline__ void mma8(float* c, const uint32_t* a, const uint32_t* b) {
    asm volatile("mma.sync.aligned.m16n8k8.row.col.f32.tf32.tf32.f32 "
                 "{%0,%1,%2,%3},{%4,%5,%6,%7},{%8,%9},{%0,%1,%2,%3};"
                 : "+f"(c[0]), "+f"(c[1]), "+f"(c[2]), "+f"(c[3])
                 : "r"(a[0]), "r"(a[1]), "r"(a[2]), "r"(a[3]), "r"(b[0]), "r"(b[1]));
}
__device__ __forceinline__ void cpasync16(uint32_t* dst, const void* src) {
    uint32_t d = (uint32_t)__cvta_generic_to_shared(dst);
    asm volatile("cp.async.ca.shared.global [%0], [%1], 16;" :: "r"(d), "l"(src));
}
#define CP_COMMIT asm volatile("cp.async.commit_group;")
#define CP_WAIT0  asm volatile("cp.async.wait_group 0;")

// swizzled word index, 32-word rows (GEMM tiles); kg = 16-byte group 0..7
#define AIDX(m,kg) ((m)*32 + (((kg) ^ ((m)&7))<<2))
// swizzled word index, 64-word rows (attention tiles)
#define SIDX(r,c) ((r)*64 + (((((c)>>2) ^ ((r)&7)))<<2) + ((c)&3))

// ============================================================
// Prepass (verbatim round 12): destinations are device symbols
// referenced in-kernel — never passed from host.
// ============================================================
__global__ __launch_bounds__(256) void cvt_x_kernel(const float* __restrict__ x) {
    const size_t i = ((size_t)blockIdx.x * 256 + threadIdx.x) * 4;
    float4 v = *(const float4*)(x + i);
    *(uint4*)(g_xa + i) = make_uint4(f2tf(v.x), f2tf(v.y), f2tf(v.z), f2tf(v.w));
}

template <int COLS>
__global__ __launch_bounds__(256) void cvt_transpose_k(const float* __restrict__ src) {
    float* dst = (COLS == 2304) ? g_wqkvT : g_woutT;
    __shared__ float tile[32][33];
    const int c0 = blockIdx.x * 32, r0 = blockIdx.y * 32;
    const int tx = threadIdx.x, ty = threadIdx.y;
#pragma unroll
    for (int u = 0; u < 4; u++)
        tile[ty + u * 8][tx] = src[(size_t)(r0 + ty + u * 8) * COLS + c0 + tx];
    __syncthreads();
#pragma unroll
    for (int u = 0; u < 4; u++) {
        const int c = c0 + ty + u * 8, r = r0 + tx;
        ((uint32_t*)dst)[(size_t)c * 768 + r] = f2tf(tile[tx][ty + u * 8]);
    }
}

// ============================================================
// GEMM core (verbatim round 12)
// ============================================================
__device__ __forceinline__ void gemm_fill(uint32_t* As, uint32_t* Bs,
                                          const float* A, const float* BT,
                                          int by128, int bx128, int kt, int tid) {
#pragma unroll
    for (int u = 0; u < 4; u++) {
        const int g = tid + u * 256;
        const int row = g >> 3, kg = g & 7;
        cpasync16(&As[AIDX(row, kg)], A + (size_t)(by128 + row) * 768 + kt + kg * 4);
        cpasync16(&Bs[AIDX(row, kg)], BT + (size_t)(bx128 + row) * 768 + kt + kg * 4);
    }
}

__device__ __forceinline__ void gemm_core(const float* A, const float* BT,
                                          float acc[2][8][4]) {
    extern __shared__ uint32_t smem[];
    uint32_t* As = smem;            // [2][128*32]
    uint32_t* Bs = smem + 8192;     // [2][128*32]
    const int tid = threadIdx.x, lane = tid & 31, warp = tid >> 5;
    const int wm = warp >> 1, wn = warp & 1;
    const int by128 = blockIdx.y * 128, bx128 = blockIdx.x * 128;

    gemm_fill(As, Bs, A, BT, by128, bx128, 0, tid);
    CP_COMMIT;

    for (int t = 0; t < 24; t++) {
        const int cur = t & 1;
        CP_WAIT0;
        __syncthreads();
        if (t < 23) {
            gemm_fill(As + (cur ^ 1) * 4096, Bs + (cur ^ 1) * 4096,
                      A, BT, by128, bx128, (t + 1) * 32, tid);
            CP_COMMIT;
        }
        const uint32_t* Ab = As + cur * 4096;
        const uint32_t* Bb = Bs + cur * 4096;
#pragma unroll
        for (int ks = 0; ks < 4; ks++) {
            uint32_t a[2][4], b[8][2];
            const int grp = ks * 2 + (lane >> 4);
#pragma unroll
            for (int i = 0; i < 2; i++) {
                const int row = wm * 32 + i * 16 + ((lane >> 3) & 1) * 8 + (lane & 7);
                ldsm4(a[i][0], a[i][1], a[i][2], a[i][3], &Ab[AIDX(row, grp)]);
            }
#pragma unroll
            for (int jp = 0; jp < 4; jp++) {
                const int row = wn * 64 + jp * 16 + ((lane >> 3) & 1) * 8 + (lane & 7);
                ldsm4(b[2 * jp][0], b[2 * jp + 1][0], b[2 * jp][1], b[2 * jp + 1][1],
                      &Bb[AIDX(row, grp)]);
            }
#pragma unroll
            for (int i = 0; i < 2; i++)
#pragma unroll
                for (int j = 0; j < 8; j++) mma8(acc[i][j], a[i], b[j]);
        }
        __syncthreads();
    }
}

// ============================================================
// Kernel 1: QKV GEMM (verbatim round 12)
// ============================================================
__global__ __launch_bounds__(256, 2) void qkv_gemm() {
    float acc[2][8][4];
#pragma unroll
    for (int i = 0; i < 2; i++)
#pragma unroll
        for (int j = 0; j < 8; j++)
#pragma unroll
            for (int r = 0; r < 4; r++) acc[i][j][r] = 0.f;

    gemm_core(g_xa, g_wqkvT, acc);

    const int tid = threadIdx.x, lane = tid & 31, warp = tid >> 5;
    const int wm = warp >> 1, wn = warp & 1;
    const int n0 = blockIdx.x * 128 + wn * 64;
    const int sec = n0 / 768;
    const int h = (n0 - sec * 768) >> 6;
#pragma unroll
    for (int i = 0; i < 2; i++)
#pragma unroll
        for (int li = 0; li < 2; li++) {
            const int m = blockIdx.y * 128 + wm * 32 + i * 16 + li * 8 + (lane >> 2);
            const int b = m >> 10, tok = m & 1023;
            if (sec == 0) {
                uint32_t* base = (uint32_t*)g_q +
                    ((size_t)(b * H_ + h) * 1024 + tok) * 64 + 2 * (lane & 3);
#pragma unroll
                for (int j = 0; j < 8; j++)
                    *(uint2*)(base + j * 8) = make_uint2(f2tf(acc[i][j][li * 2] * SCALE),
                                                         f2tf(acc[i][j][li * 2 + 1] * SCALE));
            } else if (sec == 1) {
                uint32_t* base = (uint32_t*)g_k +
                    ((size_t)(b * H_ + h) * 1024 + tok) * 64 + 2 * (lane & 3);
#pragma unroll
                for (int j = 0; j < 8; j++)
                    *(uint2*)(base + j * 8) = make_uint2(f2tf(acc[i][j][li * 2]),
                                                         f2tf(acc[i][j][li * 2 + 1]));
            } else {
                uint32_t* base = (uint32_t*)g_v + (size_t)(b * H_ + h) * 65536 + tok;
#pragma unroll
                for (int j = 0; j < 8; j++) {
                    const int d = j * 8 + 2 * (lane & 3);
                    base[(size_t)d * 1024]       = f2tf(acc[i][j][li * 2]);
                    base[(size_t)(d + 1) * 1024] = f2tf(acc[i][j][li * 2 + 1]);
                }
            }
        }
}

// ============================================================
// Kernel 2: flash attention — 128-row Q tile, 8 warps, dedicated
// P buffer (warp-private S->P hand-off), double-buffered K/V.
// smem: Qs 32K + Ks 2x16K + Vs 2x16K + Ps 32K = 128KB
// Per-row math identical to round 12 (same tiles, loop order, cvt).
// ============================================================
__device__ __forceinline__ void attn_loadKV(uint32_t* Ks, uint32_t* Vs,
                                            const float* kbase, const float* vbase,
                                            int kt, int tid) {
#pragma unroll
    for (int u = 0; u < 4; u++) {
        const int g = tid + u * 256;
        const int row = g >> 4, kg = g & 15;
        cpasync16(&Ks[SIDX(row, kg * 4)], kbase + (size_t)(kt + row) * 64 + kg * 4);
        cpasync16(&Vs[SIDX(row, kg * 4)], vbase + (size_t)row * 1024 + kt + kg * 4);
    }
}

__global__ __launch_bounds__(256) void attn_kernel() {
    extern __shared__ uint32_t smem[];
    uint32_t* Qs = smem;             // 128*64 = 8192 words
    uint32_t* Ks = smem + 8192;      // [2][64*64]
    uint32_t* Vs = smem + 16384;     // [2][64*64]
    uint32_t* Ps = smem + 24576;     // 128*64  (dedicated P buffer)
    const int tid = threadIdx.x, lane = tid & 31, warp = tid >> 5;
    const int q0 = blockIdx.x * 128, bh = blockIdx.y;
    const float* qbase = g_q + (size_t)bh * 65536 + (size_t)q0 * 64;
    const float* kbase = g_k + (size_t)bh * 65536;
    const float* vbase = g_v + (size_t)bh * 65536;

    // Q tile (already tf32 + scaled): 2048 uint4 over 256 threads
#pragma unroll
    for (int u = 0; u < 8; u++) {
        const int g = tid + u * 256;
        const int row = g >> 4, kg = g & 15;
        cpasync16(&Qs[SIDX(row, kg * 4)], qbase + (size_t)row * 64 + kg * 4);
    }
    attn_loadKV(Ks, Vs, kbase, vbase, 0, tid);
    CP_COMMIT;

    float o[8][4];
#pragma unroll
    for (int j = 0; j < 8; j++)
#pragma unroll
        for (int r = 0; r < 4; r++) o[j][r] = 0.f;
    float mA = -1e30f, mB = -1e30f, lA = 0.f, lB = 0.f;

    for (int t = 0; t < 16; t++) {
        const int cur = t & 1;
        CP_WAIT0;
        __syncthreads();       // K/V buffer ready; all warps done with prev buffers
        if (t < 15) {
            attn_loadKV(Ks + (cur ^ 1) * 4096, Vs + (cur ^ 1) * 4096,
                        kbase, vbase, (t + 1) * 64, tid);
            CP_COMMIT;
        }
        const uint32_t* Kb = Ks + cur * 4096;
        const uint32_t* Vb = Vs + cur * 4096;

        // S = Q K^T  (warp: q-rows warp*16..+15, all 64 k-cols)
        float s[8][4];
#pragma unroll
        for (int j = 0; j < 8; j++)
#pragma unroll
            for (int r = 0; r < 4; r++) s[j][r] = 0.f;
#pragma unroll
        for (int ks = 0; ks < 8; ks++) {
            uint32_t a[4], b[8][2];
            {
                const int row = warp * 16 + ((lane >> 3) & 1) * 8 + (lane & 7);
                const int grp = ks * 2 + (lane >> 4);
                ldsm4(a[0], a[1], a[2], a[3], &Qs[row * 64 + ((grp ^ (row & 7)) << 2)]);
            }
#pragma unroll
            for (int jp = 0; jp < 4; jp++) {
                const int row = jp * 16 + ((lane >> 3) & 1) * 8 + (lane & 7);
                const int grp = ks * 2 + (lane >> 4);
                ldsm4(b[2 * jp][0], b[2 * jp + 1][0], b[2 * jp][1], b[2 * jp + 1][1],
                      &Kb[row * 64 + ((grp ^ (row & 7)) << 2)]);
            }
#pragma unroll
            for (int j = 0; j < 8; j++) mma8(s[j], a, b[j]);
        }

        // online softmax (rows ra=warp*16+(lane>>2), rb=ra+8) — identical math
        float mxa = -1e30f, mxb = -1e30f;
#pragma unroll
        for (int j = 0; j < 8; j++) {
            mxa = fmaxf(mxa, fmaxf(s[j][0], s[j][1]));
            mxb = fmaxf(mxb, fmaxf(s[j][2], s[j][3]));
        }
#pragma unroll
        for (int off = 1; off <= 2; off <<= 1) {
            mxa = fmaxf(mxa, __shfl_xor_sync(0xffffffffu, mxa, off));
            mxb = fmaxf(mxb, __shfl_xor_sync(0xffffffffu, mxb, off));
        }
        const float mnA = fmaxf(mA, mxa), mnB = fmaxf(mB, mxb);
        const float facA = __expf(mA - mnA), facB = __expf(mB - mnB);
        mA = mnA; mB = mnB;
        float sa = 0.f, sb = 0.f;
#pragma unroll
        for (int j = 0; j < 8; j++) {
            s[j][0] = __expf(s[j][0] - mA); s[j][1] = __expf(s[j][1] - mA);
            s[j][2] = __expf(s[j][2] - mB); s[j][3] = __expf(s[j][3] - mB);
            sa += s[j][0] + s[j][1]; sb += s[j][2] + s[j][3];
        }
#pragma unroll
        for (int off = 1; off <= 2; off <<= 1) {
            sa += __shfl_xor_sync(0xffffffffu, sa, off);
            sb += __shfl_xor_sync(0xffffffffu, sb, off);
        }
        lA = lA * facA + sa; lB = lB * facB + sb;
#pragma unroll
        for (int j = 0; j < 8; j++) {
            o[j][0] *= facA; o[j][1] *= facA; o[j][2] *= facB; o[j][3] *= facB;
        }

        // store P (tf32) into dedicated warp-private rows of Ps
        {
            const int ra = warp * 16 + (lane >> 2), rb = ra + 8;
#pragma unroll
            for (int j = 0; j < 8; j++) {
                const int c0 = j * 8 + 2 * (lane & 3);
                *(uint2*)&Ps[SIDX(ra, c0)] = make_uint2(f2tf(s[j][0]), f2tf(s[j][1]));
                *(uint2*)&Ps[SIDX(rb, c0)] = make_uint2(f2tf(s[j][2]), f2tf(s[j][3]));
            }
        }
        __syncwarp();   // warp-private hand-off: only our own 16 rows are read back

        // O += P V  (A = own P rows, B = V^T)
#pragma unroll
        for (int ks = 0; ks < 8; ks++) {
            uint32_t a[4], b[8][2];
            {
                const int row = warp * 16 + ((lane >> 3) & 1) * 8 + (lane & 7);
                const int grp = ks * 2 + (lane >> 4);
                ldsm4(a[0], a[1], a[2], a[3], &Ps[row * 64 + ((grp ^ (row & 7)) << 2)]);
            }
#pragma unroll
            for (int jp = 0; jp < 4; jp++) {
                const int row = jp * 16 + ((lane >> 3) & 1) * 8 + (lane & 7);
                const int grp = ks * 2 + (lane >> 4);
                ldsm4(b[2 * jp][0], b[2 * jp + 1][0], b[2 * jp][1], b[2 * jp + 1][1],
                      &Vb[row * 64 + ((grp ^ (row & 7)) << 2)]);
            }
#pragma unroll
            for (int j = 0; j < 8; j++) mma8(o[j], a, b[j]);
        }
        // top-of-loop CP_WAIT0+__syncthreads orders Vb reads vs. the prefetch
        // that will overwrite this buffer at iteration t+1
    }

    // normalize + write ctx (tf32-rounded for out_gemm)
    const int b = bh / H_, h = bh - b * H_;
    const int ra = warp * 16 + (lane >> 2);
    const float invA = 1.f / lA, invB = 1.f / lB;
    uint32_t* pa = (uint32_t*)g_ctx + ((size_t)(b * 1024) + q0 + ra) * 768 + h * 64 + 2 * (lane & 3);
    uint32_t* pb = (uint32_t*)g_ctx + ((size_t)(b * 1024) + q0 + ra + 8) * 768 + h * 64 + 2 * (lane & 3);
#pragma unroll
    for (int j = 0; j < 8; j++) {
        *(uint2*)(pa + j * 8) = make_uint2(f2tf(o[j][0] * invA), f2tf(o[j][1] * invA));
        *(uint2*)(pb + j * 8) = make_uint2(f2tf(o[j][2] * invB), f2tf(o[j][3] * invB));
    }
}

// ============================================================
// Kernel 3: out projection (verbatim round 12)
// ============================================================
__global__ __launch_bounds__(256, 2) void out_gemm(const float* __restrict__ bias,
                                                   float* __restrict__ out) {
    float acc[2][8][4];
#pragma unroll
    for (int i = 0; i < 2; i++)
#pragma unroll
        for (int j = 0; j < 8; j++)
#pragma unroll
            for (int r = 0; r < 4; r++) acc[i][j][r] = 0.f;

    gemm_core(g_ctx, g_woutT, acc);

    const int tid = threadIdx.x, lane = tid & 31, warp = tid >> 5;
    const int wm = warp >> 1, wn = warp & 1;
    const int n0 = blockIdx.x * 128 + wn * 64 + 2 * (lane & 3);
#pragma unroll
    for (int i = 0; i < 2; i++)
#pragma unroll
        for (int li = 0; li < 2; li++) {
            const int m = blockIdx.y * 128 + wm * 32 + i * 16 + li * 8 + (lane >> 2);
            float* op = out + (size_t)m * 768 + n0;
#pragma unroll
            for (int j = 0; j < 8; j++) {
                float2 bb = *(const float2*)(bias + n0 + j * 8);
                *(float2*)(op + j * 8) =
                    make_float2(acc[i][j][li * 2] + bb.x, acc[i][j][li * 2 + 1] + bb.y);
            }
        }
}

// ============================================================
extern "C" void kernel_launch(void* const* d_in, const int* in_sizes, int n_in,
                              void* d_out, int out_size) {
    const float* x     = (const float*)d_in[0];
    const float* w_qkv = (const float*)d_in[1];
    const float* w_out = (const float*)d_in[2];
    const float* b_out = (const float*)d_in[3];
    float* out = (float*)d_out;

    cudaFuncSetAttribute(qkv_gemm, cudaFuncAttributeMaxDynamicSharedMemorySize, 65536);
    cudaFuncSetAttribute(out_gemm, cudaFuncAttributeMaxDynamicSharedMemorySize, 65536);
    cudaFuncSetAttribute(attn_kernel, cudaFuncAttributeMaxDynamicSharedMemorySize, 131072);

    cvt_x_kernel<<<M_ * C_ / 1024, 256>>>(x);
    cvt_transpose_k<2304><<<dim3(2304 / 32, 768 / 32), dim3(32, 8)>>>(w_qkv);
    cvt_transpose_k<768><<<dim3(768 / 32, 768 / 32), dim3(32, 8)>>>(w_out);
    qkv_gemm<<<dim3(2304 / 128, M_ / 128), 256, 65536>>>();
    attn_kernel<<<dim3(N_ / 128, BH_), 256, 131072>>>();
    out_gemm<<<dim3(768 / 128, M_ / 128), 256, 65536>>>(b_out, out);
}

// round 15
// speedup vs baseline: 2.1676x; 1.3489x over previous
#include <cuda_runtime.h>
#include <cuda_fp16.h>
#include <cstdint>

#define B_  8
#define N_  1024
#define C_  768
#define H_  12
#define HD_ 64
#define BH_ (B_*H_)          // 96
#define M_  (B_*N_)          // 8192
constexpr float SCALE = 0.125f;  // 64^-0.5

// ---- scratch ----
__device__ __half g_qh[B_*H_*N_*HD_];   // [b][h][n][d]  fp16, pre-scaled
__device__ __half g_kh[B_*H_*N_*HD_];   // [b][h][n][d]  fp16
__device__ __half g_vh[B_*H_*HD_*N_];   // [b][h][d][n]  fp16, transposed
__device__ float g_ctx[B_*N_*C_];       // [b][n][c]     tf32-rounded
__device__ float g_xa[M_*C_];           // x tf32-rounded
__device__ float g_wqkvT[3*C_*C_];      // w_qkv^T [n][k] tf32-rounded
__device__ float g_woutT[C_*C_];        // w_out^T [n][k] tf32-rounded

// ---- helpers ----
__device__ __forceinline__ uint32_t f2tf(float f) {
    uint32_t u; asm("cvt.rna.tf32.f32 %0, %1;" : "=r"(u) : "f"(f)); return u;
}
// pack two floats to f16x2 word: lo <- a, hi <- b
__device__ __forceinline__ uint32_t pack_f16x2(float a, float b) {
    uint32_t u; asm("cvt.rn.f16x2.f32 %0, %1, %2;" : "=r"(u) : "f"(b), "f"(a)); return u;
}
__device__ __forceinline__ void ldsm4(uint32_t& r0, uint32_t& r1, uint32_t& r2, uint32_t& r3,
                                      const uint32_t* p) {
    uint32_t a = (uint32_t)__cvta_generic_to_shared(p);
    asm volatile("ldmatrix.sync.aligned.m8n8.x4.shared.b16 {%0,%1,%2,%3}, [%4];"
                 : "=r"(r0), "=r"(r1), "=r"(r2), "=r"(r3) : "r"(a));
}
__device__ __forceinline__ void mma8(float* c, const uint32_t* a, const uint32_t* b) {
    asm volatile("mma.sync.aligned.m16n8k8.row.col.f32.tf32.tf32.f32 "
                 "{%0,%1,%2,%3},{%4,%5,%6,%7},{%8,%9},{%0,%1,%2,%3};"
                 : "+f"(c[0]), "+f"(c[1]), "+f"(c[2]), "+f"(c[3])
                 : "r"(a[0]), "r"(a[1]), "r"(a[2]), "r"(a[3]), "r"(b[0]), "r"(b[1]));
}
__device__ __forceinline__ void mma16(float* c, const uint32_t* a, const uint32_t* b) {
    asm volatile("mma.sync.aligned.m16n8k16.row.col.f32.f16.f16.f32 "
                 "{%0,%1,%2,%3},{%4,%5,%6,%7},{%8,%9},{%0,%1,%2,%3};"
                 : "+f"(c[0]), "+f"(c[1]), "+f"(c[2]), "+f"(c[3])
                 : "r"(a[0]), "r"(a[1]), "r"(a[2]), "r"(a[3]), "r"(b[0]), "r"(b[1]));
}
__device__ __forceinline__ void cpasync16(uint32_t* dst, const void* src) {
    uint32_t d = (uint32_t)__cvta_generic_to_shared(dst);
    asm volatile("cp.async.ca.shared.global [%0], [%1], 16;" :: "r"(d), "l"(src));
}
#define CP_COMMIT asm volatile("cp.async.commit_group;")
#define CP_WAIT0  asm volatile("cp.async.wait_group 0;")

// swizzled word index, 32-word rows (GEMM tiles); kg = 16-byte group 0..7
#define AIDX(m,kg) ((m)*32 + (((kg) ^ ((m)&7))<<2))
// half tiles: 64 halfs = 32 words per row; granule g 0..7; word index
#define HG(r,g) ((r)*32 + ((((g) ^ ((r)&7)))<<2))

// ============================================================
// Prepass (verbatim round 13): device-symbol destinations in-kernel.
// ============================================================
__global__ __launch_bounds__(256) void cvt_x_kernel(const float* __restrict__ x) {
    const size_t i = ((size_t)blockIdx.x * 256 + threadIdx.x) * 4;
    float4 v = *(const float4*)(x + i);
    *(uint4*)(g_xa + i) = make_uint4(f2tf(v.x), f2tf(v.y), f2tf(v.z), f2tf(v.w));
}

template <int COLS>
__global__ __launch_bounds__(256) void cvt_transpose_k(const float* __restrict__ src) {
    float* dst = (COLS == 2304) ? g_wqkvT : g_woutT;
    __shared__ float tile[32][33];
    const int c0 = blockIdx.x * 32, r0 = blockIdx.y * 32;
    const int tx = threadIdx.x, ty = threadIdx.y;
#pragma unroll
    for (int u = 0; u < 4; u++)
        tile[ty + u * 8][tx] = src[(size_t)(r0 + ty + u * 8) * COLS + c0 + tx];
    __syncthreads();
#pragma unroll
    for (int u = 0; u < 4; u++) {
        const int c = c0 + ty + u * 8, r = r0 + tx;
        ((uint32_t*)dst)[(size_t)c * 768 + r] = f2tf(tile[tx][ty + u * 8]);
    }
}

// ============================================================
// GEMM core (verbatim round 13)
// ============================================================
__device__ __forceinline__ void gemm_fill(uint32_t* As, uint32_t* Bs,
                                          const float* A, const float* BT,
                                          int by128, int bx128, int kt, int tid) {
#pragma unroll
    for (int u = 0; u < 4; u++) {
        const int g = tid + u * 256;
        const int row = g >> 3, kg = g & 7;
        cpasync16(&As[AIDX(row, kg)], A + (size_t)(by128 + row) * 768 + kt + kg * 4);
        cpasync16(&Bs[AIDX(row, kg)], BT + (size_t)(bx128 + row) * 768 + kt + kg * 4);
    }
}

__device__ __forceinline__ void gemm_core(const float* A, const float* BT,
                                          float acc[2][8][4]) {
    extern __shared__ uint32_t smem[];
    uint32_t* As = smem;            // [2][128*32]
    uint32_t* Bs = smem + 8192;     // [2][128*32]
    const int tid = threadIdx.x, lane = tid & 31, warp = tid >> 5;
    const int wm = warp >> 1, wn = warp & 1;
    const int by128 = blockIdx.y * 128, bx128 = blockIdx.x * 128;

    gemm_fill(As, Bs, A, BT, by128, bx128, 0, tid);
    CP_COMMIT;

    for (int t = 0; t < 24; t++) {
        const int cur = t & 1;
        CP_WAIT0;
        __syncthreads();
        if (t < 23) {
            gemm_fill(As + (cur ^ 1) * 4096, Bs + (cur ^ 1) * 4096,
                      A, BT, by128, bx128, (t + 1) * 32, tid);
            CP_COMMIT;
        }
        const uint32_t* Ab = As + cur * 4096;
        const uint32_t* Bb = Bs + cur * 4096;
#pragma unroll
        for (int ks = 0; ks < 4; ks++) {
            uint32_t a[2][4], b[8][2];
            const int grp = ks * 2 + (lane >> 4);
#pragma unroll
            for (int i = 0; i < 2; i++) {
                const int row = wm * 32 + i * 16 + ((lane >> 3) & 1) * 8 + (lane & 7);
                ldsm4(a[i][0], a[i][1], a[i][2], a[i][3], &Ab[AIDX(row, grp)]);
            }
#pragma unroll
            for (int jp = 0; jp < 4; jp++) {
                const int row = wn * 64 + jp * 16 + ((lane >> 3) & 1) * 8 + (lane & 7);
                ldsm4(b[2 * jp][0], b[2 * jp + 1][0], b[2 * jp][1], b[2 * jp + 1][1],
                      &Bb[AIDX(row, grp)]);
            }
#pragma unroll
            for (int i = 0; i < 2; i++)
#pragma unroll
                for (int j = 0; j < 8; j++) mma8(acc[i][j], a[i], b[j]);
        }
        __syncthreads();
    }
}

// ============================================================
// Kernel 1: QKV GEMM -> g_qh (scaled) / g_kh / g_vh (transposed), fp16
// ============================================================
__global__ __launch_bounds__(256, 2) void qkv_gemm() {
    float acc[2][8][4];
#pragma unroll
    for (int i = 0; i < 2; i++)
#pragma unroll
        for (int j = 0; j < 8; j++)
#pragma unroll
            for (int r = 0; r < 4; r++) acc[i][j][r] = 0.f;

    gemm_core(g_xa, g_wqkvT, acc);

    const int tid = threadIdx.x, lane = tid & 31, warp = tid >> 5;
    const int wm = warp >> 1, wn = warp & 1;
    const int n0 = blockIdx.x * 128 + wn * 64;
    const int sec = n0 / 768;
    const int h = (n0 - sec * 768) >> 6;
#pragma unroll
    for (int i = 0; i < 2; i++)
#pragma unroll
        for (int li = 0; li < 2; li++) {
            const int m = blockIdx.y * 128 + wm * 32 + i * 16 + li * 8 + (lane >> 2);
            const int b = m >> 10, tok = m & 1023;
            if (sec == 0) {
                uint32_t* base = (uint32_t*)g_qh +
                    ((size_t)(b * H_ + h) * 1024 + tok) * 32 + (lane & 3);
#pragma unroll
                for (int j = 0; j < 8; j++)
                    base[j * 4] = pack_f16x2(acc[i][j][li * 2] * SCALE,
                                             acc[i][j][li * 2 + 1] * SCALE);
            } else if (sec == 1) {
                uint32_t* base = (uint32_t*)g_kh +
                    ((size_t)(b * H_ + h) * 1024 + tok) * 32 + (lane & 3);
#pragma unroll
                for (int j = 0; j < 8; j++)
                    base[j * 4] = pack_f16x2(acc[i][j][li * 2], acc[i][j][li * 2 + 1]);
            } else {
                __half* base = g_vh + (size_t)(b * H_ + h) * 65536 + tok;
#pragma unroll
                for (int j = 0; j < 8; j++) {
                    const int d = j * 8 + 2 * (lane & 3);
                    base[(size_t)d * 1024]       = __float2half_rn(acc[i][j][li * 2]);
                    base[(size_t)(d + 1) * 1024] = __float2half_rn(acc[i][j][li * 2 + 1]);
                }
            }
        }
}

// ============================================================
// Kernel 2: flash attention fp16 — 128-row Q tile, 8 warps,
// dedicated P buffer, double-buffered K/V, m16n8k16 MMAs.
// smem: Q 16K + K 2x8K + V 2x8K + P 16K = 64KB -> 2 CTAs/SM.
// ============================================================
__device__ __forceinline__ void attn_loadKV(uint32_t* Ks, uint32_t* Vs,
                                            const __half* kbase, const __half* vbase,
                                            int kt, int tid) {
#pragma unroll
    for (int u = 0; u < 2; u++) {
        const int g = tid + u * 256;
        const int row = g >> 3, kg = g & 7;
        cpasync16(&Ks[HG(row, kg)], kbase + (size_t)(kt + row) * 64 + kg * 8);
        cpasync16(&Vs[HG(row, kg)], vbase + (size_t)row * 1024 + kt + kg * 8);
    }
}

__global__ __launch_bounds__(256, 2) void attn_kernel() {
    extern __shared__ uint32_t smem[];
    uint32_t* Qs = smem;             // 128*32 = 4096 words (fp16 128x64)
    uint32_t* Ks = smem + 4096;      // [2][64*32]
    uint32_t* Vs = smem + 8192;      // [2][64*32]
    uint32_t* Ps = smem + 12288;     // 128*32 (fp16 128x64)
    const int tid = threadIdx.x, lane = tid & 31, warp = tid >> 5;
    const int q0 = blockIdx.x * 128, bh = blockIdx.y;
    const __half* qbase = g_qh + (size_t)bh * 65536 + (size_t)q0 * 64;
    const __half* kbase = g_kh + (size_t)bh * 65536;
    const __half* vbase = g_vh + (size_t)bh * 65536;

    // Q tile: 128 rows x 8 granules = 1024 granules
#pragma unroll
    for (int u = 0; u < 4; u++) {
        const int g = tid + u * 256;
        const int row = g >> 3, kg = g & 7;
        cpasync16(&Qs[HG(row, kg)], qbase + (size_t)row * 64 + kg * 8);
    }
    attn_loadKV(Ks, Vs, kbase, vbase, 0, tid);
    CP_COMMIT;

    float o[8][4];
#pragma unroll
    for (int j = 0; j < 8; j++)
#pragma unroll
        for (int r = 0; r < 4; r++) o[j][r] = 0.f;
    float mA = -1e30f, mB = -1e30f, lA = 0.f, lB = 0.f;

    // per-lane ldmatrix addressing constants
    const int lrow = (lane & 7) + ((lane >> 3) & 1) * 8;  // row within 16
    const int lgr  = lane >> 4;                           // granule select 0/1

    for (int t = 0; t < 16; t++) {
        const int cur = t & 1;
        CP_WAIT0;
        __syncthreads();
        if (t < 15) {
            attn_loadKV(Ks + (cur ^ 1) * 2048, Vs + (cur ^ 1) * 2048,
                        kbase, vbase, (t + 1) * 64, tid);
            CP_COMMIT;
        }
        const uint32_t* Kb = Ks + cur * 2048;
        const uint32_t* Vb = Vs + cur * 2048;

        // S = Q K^T  (fp16 m16n8k16; kc over d in 4 chunks of 16)
        float s[8][4];
#pragma unroll
        for (int j = 0; j < 8; j++)
#pragma unroll
            for (int r = 0; r < 4; r++) s[j][r] = 0.f;
#pragma unroll
        for (int kc = 0; kc < 4; kc++) {
            uint32_t a[4], b[8][2];
            const int g = kc * 2 + lgr;
            {
                const int row = warp * 16 + lrow;
                ldsm4(a[0], a[1], a[2], a[3], &Qs[HG(row, g)]);
            }
#pragma unroll
            for (int jp = 0; jp < 4; jp++) {
                const int row = jp * 16 + lrow;
                ldsm4(b[2 * jp][0], b[2 * jp + 1][0], b[2 * jp][1], b[2 * jp + 1][1],
                      &Kb[HG(row, g)]);
            }
#pragma unroll
            for (int j = 0; j < 8; j++) mma16(s[j], a, b[j]);
        }

        // online softmax (identical math to round 13)
        float mxa = -1e30f, mxb = -1e30f;
#pragma unroll
        for (int j = 0; j < 8; j++) {
            mxa = fmaxf(mxa, fmaxf(s[j][0], s[j][1]));
            mxb = fmaxf(mxb, fmaxf(s[j][2], s[j][3]));
        }
#pragma unroll
        for (int off = 1; off <= 2; off <<= 1) {
            mxa = fmaxf(mxa, __shfl_xor_sync(0xffffffffu, mxa, off));
            mxb = fmaxf(mxb, __shfl_xor_sync(0xffffffffu, mxb, off));
        }
        const float mnA = fmaxf(mA, mxa), mnB = fmaxf(mB, mxb);
        const float facA = __expf(mA - mnA), facB = __expf(mB - mnB);
        mA = mnA; mB = mnB;
        float sa = 0.f, sb = 0.f;
#pragma unroll
        for (int j = 0; j < 8; j++) {
            s[j][0] = __expf(s[j][0] - mA); s[j][1] = __expf(s[j][1] - mA);
            s[j][2] = __expf(s[j][2] - mB); s[j][3] = __expf(s[j][3] - mB);
            sa += s[j][0] + s[j][1]; sb += s[j][2] + s[j][3];
        }
#pragma unroll
        for (int off = 1; off <= 2; off <<= 1) {
            sa += __shfl_xor_sync(0xffffffffu, sa, off);
            sb += __shfl_xor_sync(0xffffffffu, sb, off);
        }
        lA = lA * facA + sa; lB = lB * facB + sb;
#pragma unroll
        for (int j = 0; j < 8; j++) {
            o[j][0] *= facA; o[j][1] *= facA; o[j][2] *= facB; o[j][3] *= facB;
        }

        // store P (fp16) into warp-private rows of Ps:
        // cols j*8+2(lane&3) -> word (lane&3) within granule j
        {
            const int ra = warp * 16 + (lane >> 2), rb = ra + 8;
#pragma unroll
            for (int j = 0; j < 8; j++) {
                Ps[HG(ra, j) + (lane & 3)] = pack_f16x2(s[j][0], s[j][1]);
                Ps[HG(rb, j) + (lane & 3)] = pack_f16x2(s[j][2], s[j][3]);
            }
        }
        __syncwarp();

        // O += P V  (A = own P rows; B = V^T tile [d][tok]; kc over tok)
#pragma unroll
        for (int kc = 0; kc < 4; kc++) {
            uint32_t a[4], b[8][2];
            const int g = kc * 2 + lgr;
            {
                const int row = warp * 16 + lrow;
                ldsm4(a[0], a[1], a[2], a[3], &Ps[HG(row, g)]);
            }
#pragma unroll
            for (int jp = 0; jp < 4; jp++) {
                const int row = jp * 16 + lrow;
                ldsm4(b[2 * jp][0], b[2 * jp + 1][0], b[2 * jp][1], b[2 * jp + 1][1],
                      &Vb[HG(row, g)]);
            }
#pragma unroll
            for (int j = 0; j < 8; j++) mma16(o[j], a, b[j]);
        }
        // top-of-loop CP_WAIT0 + __syncthreads orders Vb/Kb reads vs. the
        // prefetch that overwrites this buffer next iteration
    }

    // normalize + write ctx (tf32-rounded for out_gemm) — unchanged
    const int b = bh / H_, h = bh - b * H_;
    const int ra = warp * 16 + (lane >> 2);
    const float invA = 1.f / lA, invB = 1.f / lB;
    uint32_t* pa = (uint32_t*)g_ctx + ((size_t)(b * 1024) + q0 + ra) * 768 + h * 64 + 2 * (lane & 3);
    uint32_t* pb = (uint32_t*)g_ctx + ((size_t)(b * 1024) + q0 + ra + 8) * 768 + h * 64 + 2 * (lane & 3);
#pragma unroll
    for (int j = 0; j < 8; j++) {
        *(uint2*)(pa + j * 8) = make_uint2(f2tf(o[j][0] * invA), f2tf(o[j][1] * invA));
        *(uint2*)(pb + j * 8) = make_uint2(f2tf(o[j][2] * invB), f2tf(o[j][3] * invB));
    }
}

// ============================================================
// Kernel 3: out projection (verbatim round 13)
// ============================================================
__global__ __launch_bounds__(256, 2) void out_gemm(const float* __restrict__ bias,
                                                   float* __restrict__ out) {
    float acc[2][8][4];
#pragma unroll
    for (int i = 0; i < 2; i++)
#pragma unroll
        for (int j = 0; j < 8; j++)
#pragma unroll
            for (int r = 0; r < 4; r++) acc[i][j][r] = 0.f;

    gemm_core(g_ctx, g_woutT, acc);

    const int tid = threadIdx.x, lane = tid & 31, warp = tid >> 5;
    const int wm = warp >> 1, wn = warp & 1;
    const int n0 = blockIdx.x * 128 + wn * 64 + 2 * (lane & 3);
#pragma unroll
    for (int i = 0; i < 2; i++)
#pragma unroll
        for (int li = 0; li < 2; li++) {
            const int m = blockIdx.y * 128 + wm * 32 + i * 16 + li * 8 + (lane >> 2);
            float* op = out + (size_t)m * 768 + n0;
#pragma unroll
            for (int j = 0; j < 8; j++) {
                float2 bb = *(const float2*)(bias + n0 + j * 8);
                *(float2*)(op + j * 8) =
                    make_float2(acc[i][j][li * 2] + bb.x, acc[i][j][li * 2 + 1] + bb.y);
            }
        }
}

// ============================================================
extern "C" void kernel_launch(void* const* d_in, const int* in_sizes, int n_in,
                              void* d_out, int out_size) {
    const float* x     = (const float*)d_in[0];
    const float* w_qkv = (const float*)d_in[1];
    const float* w_out = (const float*)d_in[2];
    const float* b_out = (const float*)d_in[3];
    float* out = (float*)d_out;

    cudaFuncSetAttribute(qkv_gemm, cudaFuncAttributeMaxDynamicSharedMemorySize, 65536);
    cudaFuncSetAttribute(out_gemm, cudaFuncAttributeMaxDynamicSharedMemorySize, 65536);
    cudaFuncSetAttribute(attn_kernel, cudaFuncAttributeMaxDynamicSharedMemorySize, 65536);

    cvt_x_kernel<<<M_ * C_ / 1024, 256>>>(x);
    cvt_transpose_k<2304><<<dim3(2304 / 32, 768 / 32), dim3(32, 8)>>>(w_qkv);
    cvt_transpose_k<768><<<dim3(768 / 32, 768 / 32), dim3(32, 8)>>>(w_out);
    qkv_gemm<<<dim3(2304 / 128, M_ / 128), 256, 65536>>>();
    attn_kernel<<<dim3(N_ / 128, BH_), 256, 65536>>>();
    out_gemm<<<dim3(768 / 128, M_ / 128), 256, 65536>>>(b_out, out);
}

// round 16
// speedup vs baseline: 3.0422x; 1.4035x over previous
#include <cuda_runtime.h>
#include <cuda_fp16.h>
#include <cstdint>

#define B_  8
#define N_  1024
#define C_  768
#define H_  12
#define HD_ 64
#define BH_ (B_*H_)          // 96
#define M_  (B_*N_)          // 8192
constexpr float SCALE = 0.125f;  // 64^-0.5

// ---- scratch (all fp16 operand chains) ----
__device__ __half g_qh[B_*H_*N_*HD_];   // [b][h][n][d]  fp16, pre-scaled
__device__ __half g_kh[B_*H_*N_*HD_];   // [b][h][n][d]  fp16
__device__ __half g_vh[B_*H_*HD_*N_];   // [b][h][d][n]  fp16, transposed
__device__ __half g_ctxh[B_*N_*C_];     // [b][n][c]     fp16
__device__ __half g_xh[M_*C_];          // x fp16
__device__ __half g_wqkvTh[3*C_*C_];    // w_qkv^T [n][k] fp16
__device__ __half g_woutTh[C_*C_];      // w_out^T [n][k] fp16

// ---- helpers ----
// pack two floats to f16x2 word: lo <- a, hi <- b
__device__ __forceinline__ uint32_t pack_f16x2(float a, float b) {
    uint32_t u; asm("cvt.rn.f16x2.f32 %0, %1, %2;" : "=r"(u) : "f"(b), "f"(a)); return u;
}
__device__ __forceinline__ void ldsm4(uint32_t& r0, uint32_t& r1, uint32_t& r2, uint32_t& r3,
                                      const uint32_t* p) {
    uint32_t a = (uint32_t)__cvta_generic_to_shared(p);
    asm volatile("ldmatrix.sync.aligned.m8n8.x4.shared.b16 {%0,%1,%2,%3}, [%4];"
                 : "=r"(r0), "=r"(r1), "=r"(r2), "=r"(r3) : "r"(a));
}
__device__ __forceinline__ void mma16(float* c, const uint32_t* a, const uint32_t* b) {
    asm volatile("mma.sync.aligned.m16n8k16.row.col.f32.f16.f16.f32 "
                 "{%0,%1,%2,%3},{%4,%5,%6,%7},{%8,%9},{%0,%1,%2,%3};"
                 : "+f"(c[0]), "+f"(c[1]), "+f"(c[2]), "+f"(c[3])
                 : "r"(a[0]), "r"(a[1]), "r"(a[2]), "r"(a[3]), "r"(b[0]), "r"(b[1]));
}
__device__ __forceinline__ void cpasync16(uint32_t* dst, const void* src) {
    uint32_t d = (uint32_t)__cvta_generic_to_shared(dst);
    asm volatile("cp.async.ca.shared.global [%0], [%1], 16;" :: "r"(d), "l"(src));
}
#define CP_COMMIT asm volatile("cp.async.commit_group;")
#define CP_WAIT0  asm volatile("cp.async.wait_group 0;")

// half tiles: 64 halfs = 32 words per row; granule g 0..7 (8 halfs); word index
#define HG(r,g) ((r)*32 + ((((g) ^ ((r)&7)))<<2))

// ============================================================
// Prepass: fp32 -> fp16 (x), fp32 -> fp16 + transpose (weights).
// Destinations are device symbols referenced in-kernel.
// ============================================================
__global__ __launch_bounds__(256) void cvt_x_h(const float* __restrict__ x) {
    const size_t i = ((size_t)blockIdx.x * 256 + threadIdx.x) * 8;
    float4 v0 = *(const float4*)(x + i);
    float4 v1 = *(const float4*)(x + i + 4);
    uint4 t = make_uint4(pack_f16x2(v0.x, v0.y), pack_f16x2(v0.z, v0.w),
                         pack_f16x2(v1.x, v1.y), pack_f16x2(v1.z, v1.w));
    *(uint4*)((uint32_t*)g_xh + i / 2) = t;
}

// src [768][COLS] row-major -> dst [COLS][768] fp16
template <int COLS>
__global__ __launch_bounds__(256) void cvt_transpose_h(const float* __restrict__ src) {
    __half* dst = (COLS == 2304) ? g_wqkvTh : g_woutTh;
    __shared__ float tile[32][33];
    const int c0 = blockIdx.x * 32, r0 = blockIdx.y * 32;
    const int tx = threadIdx.x, ty = threadIdx.y;
#pragma unroll
    for (int u = 0; u < 4; u++)
        tile[ty + u * 8][tx] = src[(size_t)(r0 + ty + u * 8) * COLS + c0 + tx];
    __syncthreads();
#pragma unroll
    for (int u = 0; u < 4; u++) {
        const int c = c0 + ty + u * 8, r = r0 + tx;
        dst[(size_t)c * 768 + r] = __float2half_rn(tile[tx][ty + u * 8]);
    }
}

// ============================================================
// GEMM core fp16: 128x128x64 tiles, double-buffered cp.async,
// HG layout + attention-proven m16n8k16 fragment mapping.
// A [m][k] k-major fp16, BT [n][k] k-major fp16, K=768.
// smem: 2 x (A 16KB + B 16KB) = 64KB
// ============================================================
__device__ __forceinline__ void gemm_fill_h(uint32_t* As, uint32_t* Bs,
                                            const __half* A, const __half* BT,
                                            int by128, int bx128, int kt, int tid) {
#pragma unroll
    for (int u = 0; u < 4; u++) {
        const int g = tid + u * 256;
        const int row = g >> 3, kg = g & 7;
        cpasync16(&As[HG(row, kg)], A + (size_t)(by128 + row) * 768 + kt + kg * 8);
        cpasync16(&Bs[HG(row, kg)], BT + (size_t)(bx128 + row) * 768 + kt + kg * 8);
    }
}

__device__ __forceinline__ void gemm_core_h(const __half* A, const __half* BT,
                                            float acc[2][8][4]) {
    extern __shared__ uint32_t smem[];
    uint32_t* As = smem;            // [2][128*32]
    uint32_t* Bs = smem + 8192;     // [2][128*32]
    const int tid = threadIdx.x, lane = tid & 31, warp = tid >> 5;
    const int wm = warp >> 1, wn = warp & 1;
    const int by128 = blockIdx.y * 128, bx128 = blockIdx.x * 128;
    const int lrow = (lane & 7) + ((lane >> 3) & 1) * 8;
    const int lgr  = lane >> 4;

    gemm_fill_h(As, Bs, A, BT, by128, bx128, 0, tid);
    CP_COMMIT;

    for (int t = 0; t < 12; t++) {
        const int cur = t & 1;
        CP_WAIT0;
        __syncthreads();
        if (t < 11) {
            gemm_fill_h(As + (cur ^ 1) * 4096, Bs + (cur ^ 1) * 4096,
                        A, BT, by128, bx128, (t + 1) * 64, tid);
            CP_COMMIT;
        }
        const uint32_t* Ab = As + cur * 4096;
        const uint32_t* Bb = Bs + cur * 4096;
#pragma unroll
        for (int kc = 0; kc < 4; kc++) {
            uint32_t a[2][4], b[8][2];
            const int gg = kc * 2 + lgr;
#pragma unroll
            for (int i = 0; i < 2; i++) {
                const int row = wm * 32 + i * 16 + lrow;
                ldsm4(a[i][0], a[i][1], a[i][2], a[i][3], &Ab[HG(row, gg)]);
            }
#pragma unroll
            for (int jp = 0; jp < 4; jp++) {
                const int row = wn * 64 + jp * 16 + lrow;
                ldsm4(b[2 * jp][0], b[2 * jp + 1][0], b[2 * jp][1], b[2 * jp + 1][1],
                      &Bb[HG(row, gg)]);
            }
#pragma unroll
            for (int i = 0; i < 2; i++)
#pragma unroll
                for (int j = 0; j < 8; j++) mma16(acc[i][j], a[i], b[j]);
        }
        __syncthreads();
    }
}

// ============================================================
// Kernel 1: QKV GEMM -> g_qh (scaled) / g_kh / g_vh (transposed), fp16
// ============================================================
__global__ __launch_bounds__(256, 2) void qkv_gemm() {
    float acc[2][8][4];
#pragma unroll
    for (int i = 0; i < 2; i++)
#pragma unroll
        for (int j = 0; j < 8; j++)
#pragma unroll
            for (int r = 0; r < 4; r++) acc[i][j][r] = 0.f;

    gemm_core_h(g_xh, g_wqkvTh, acc);

    const int tid = threadIdx.x, lane = tid & 31, warp = tid >> 5;
    const int wm = warp >> 1, wn = warp & 1;
    const int n0 = blockIdx.x * 128 + wn * 64;
    const int sec = n0 / 768;
    const int h = (n0 - sec * 768) >> 6;
#pragma unroll
    for (int i = 0; i < 2; i++)
#pragma unroll
        for (int li = 0; li < 2; li++) {
            const int m = blockIdx.y * 128 + wm * 32 + i * 16 + li * 8 + (lane >> 2);
            const int b = m >> 10, tok = m & 1023;
            if (sec == 0) {
                uint32_t* base = (uint32_t*)g_qh +
                    ((size_t)(b * H_ + h) * 1024 + tok) * 32 + (lane & 3);
#pragma unroll
                for (int j = 0; j < 8; j++)
                    base[j * 4] = pack_f16x2(acc[i][j][li * 2] * SCALE,
                                             acc[i][j][li * 2 + 1] * SCALE);
            } else if (sec == 1) {
                uint32_t* base = (uint32_t*)g_kh +
                    ((size_t)(b * H_ + h) * 1024 + tok) * 32 + (lane & 3);
#pragma unroll
                for (int j = 0; j < 8; j++)
                    base[j * 4] = pack_f16x2(acc[i][j][li * 2], acc[i][j][li * 2 + 1]);
            } else {
                __half* base = g_vh + (size_t)(b * H_ + h) * 65536 + tok;
#pragma unroll
                for (int j = 0; j < 8; j++) {
                    const int d = j * 8 + 2 * (lane & 3);
                    base[(size_t)d * 1024]       = __float2half_rn(acc[i][j][li * 2]);
                    base[(size_t)(d + 1) * 1024] = __float2half_rn(acc[i][j][li * 2 + 1]);
                }
            }
        }
}

// ============================================================
// Kernel 2: flash attention fp16 (round-15 verbatim except fp16 ctx write)
// ============================================================
__device__ __forceinline__ void attn_loadKV(uint32_t* Ks, uint32_t* Vs,
                                            const __half* kbase, const __half* vbase,
                                            int kt, int tid) {
#pragma unroll
    for (int u = 0; u < 2; u++) {
        const int g = tid + u * 256;
        const int row = g >> 3, kg = g & 7;
        cpasync16(&Ks[HG(row, kg)], kbase + (size_t)(kt + row) * 64 + kg * 8);
        cpasync16(&Vs[HG(row, kg)], vbase + (size_t)row * 1024 + kt + kg * 8);
    }
}

__global__ __launch_bounds__(256, 2) void attn_kernel() {
    extern __shared__ uint32_t smem[];
    uint32_t* Qs = smem;             // 128*32
    uint32_t* Ks = smem + 4096;      // [2][64*32]
    uint32_t* Vs = smem + 8192;      // [2][64*32]
    uint32_t* Ps = smem + 12288;     // 128*32
    const int tid = threadIdx.x, lane = tid & 31, warp = tid >> 5;
    const int q0 = blockIdx.x * 128, bh = blockIdx.y;
    const __half* qbase = g_qh + (size_t)bh * 65536 + (size_t)q0 * 64;
    const __half* kbase = g_kh + (size_t)bh * 65536;
    const __half* vbase = g_vh + (size_t)bh * 65536;

#pragma unroll
    for (int u = 0; u < 4; u++) {
        const int g = tid + u * 256;
        const int row = g >> 3, kg = g & 7;
        cpasync16(&Qs[HG(row, kg)], qbase + (size_t)row * 64 + kg * 8);
    }
    attn_loadKV(Ks, Vs, kbase, vbase, 0, tid);
    CP_COMMIT;

    float o[8][4];
#pragma unroll
    for (int j = 0; j < 8; j++)
#pragma unroll
        for (int r = 0; r < 4; r++) o[j][r] = 0.f;
    float mA = -1e30f, mB = -1e30f, lA = 0.f, lB = 0.f;

    const int lrow = (lane & 7) + ((lane >> 3) & 1) * 8;
    const int lgr  = lane >> 4;

    for (int t = 0; t < 16; t++) {
        const int cur = t & 1;
        CP_WAIT0;
        __syncthreads();
        if (t < 15) {
            attn_loadKV(Ks + (cur ^ 1) * 2048, Vs + (cur ^ 1) * 2048,
                        kbase, vbase, (t + 1) * 64, tid);
            CP_COMMIT;
        }
        const uint32_t* Kb = Ks + cur * 2048;
        const uint32_t* Vb = Vs + cur * 2048;

        // S = Q K^T
        float s[8][4];
#pragma unroll
        for (int j = 0; j < 8; j++)
#pragma unroll
            for (int r = 0; r < 4; r++) s[j][r] = 0.f;
#pragma unroll
        for (int kc = 0; kc < 4; kc++) {
            uint32_t a[4], b[8][2];
            const int g = kc * 2 + lgr;
            {
                const int row = warp * 16 + lrow;
                ldsm4(a[0], a[1], a[2], a[3], &Qs[HG(row, g)]);
            }
#pragma unroll
            for (int jp = 0; jp < 4; jp++) {
                const int row = jp * 16 + lrow;
                ldsm4(b[2 * jp][0], b[2 * jp + 1][0], b[2 * jp][1], b[2 * jp + 1][1],
                      &Kb[HG(row, g)]);
            }
#pragma unroll
            for (int j = 0; j < 8; j++) mma16(s[j], a, b[j]);
        }

        // online softmax
        float mxa = -1e30f, mxb = -1e30f;
#pragma unroll
        for (int j = 0; j < 8; j++) {
            mxa = fmaxf(mxa, fmaxf(s[j][0], s[j][1]));
            mxb = fmaxf(mxb, fmaxf(s[j][2], s[j][3]));
        }
#pragma unroll
        for (int off = 1; off <= 2; off <<= 1) {
            mxa = fmaxf(mxa, __shfl_xor_sync(0xffffffffu, mxa, off));
            mxb = fmaxf(mxb, __shfl_xor_sync(0xffffffffu, mxb, off));
        }
        const float mnA = fmaxf(mA, mxa), mnB = fmaxf(mB, mxb);
        const float facA = __expf(mA - mnA), facB = __expf(mB - mnB);
        mA = mnA; mB = mnB;
        float sa = 0.f, sb = 0.f;
#pragma unroll
        for (int j = 0; j < 8; j++) {
            s[j][0] = __expf(s[j][0] - mA); s[j][1] = __expf(s[j][1] - mA);
            s[j][2] = __expf(s[j][2] - mB); s[j][3] = __expf(s[j][3] - mB);
            sa += s[j][0] + s[j][1]; sb += s[j][2] + s[j][3];
        }
#pragma unroll
        for (int off = 1; off <= 2; off <<= 1) {
            sa += __shfl_xor_sync(0xffffffffu, sa, off);
            sb += __shfl_xor_sync(0xffffffffu, sb, off);
        }
        lA = lA * facA + sa; lB = lB * facB + sb;
#pragma unroll
        for (int j = 0; j < 8; j++) {
            o[j][0] *= facA; o[j][1] *= facA; o[j][2] *= facB; o[j][3] *= facB;
        }

        // store P (fp16) into warp-private rows of Ps
        {
            const int ra = warp * 16 + (lane >> 2), rb = ra + 8;
#pragma unroll
            for (int j = 0; j < 8; j++) {
                Ps[HG(ra, j) + (lane & 3)] = pack_f16x2(s[j][0], s[j][1]);
                Ps[HG(rb, j) + (lane & 3)] = pack_f16x2(s[j][2], s[j][3]);
            }
        }
        __syncwarp();

        // O += P V
#pragma unroll
        for (int kc = 0; kc < 4; kc++) {
            uint32_t a[4], b[8][2];
            const int g = kc * 2 + lgr;
            {
                const int row = warp * 16 + lrow;
                ldsm4(a[0], a[1], a[2], a[3], &Ps[HG(row, g)]);
            }
#pragma unroll
            for (int jp = 0; jp < 4; jp++) {
                const int row = jp * 16 + lrow;
                ldsm4(b[2 * jp][0], b[2 * jp + 1][0], b[2 * jp][1], b[2 * jp + 1][1],
                      &Vb[HG(row, g)]);
            }
#pragma unroll
            for (int j = 0; j < 8; j++) mma16(o[j], a, b[j]);
        }
    }

    // normalize + write ctx as fp16 (for fp16 out_gemm)
    const int b = bh / H_, h = bh - b * H_;
    const int ra = warp * 16 + (lane >> 2);
    const float invA = 1.f / lA, invB = 1.f / lB;
    uint32_t* pa = (uint32_t*)g_ctxh + ((size_t)(b * 1024) + q0 + ra) * 384 + h * 32 + (lane & 3);
    uint32_t* pb = (uint32_t*)g_ctxh + ((size_t)(b * 1024) + q0 + ra + 8) * 384 + h * 32 + (lane & 3);
#pragma unroll
    for (int j = 0; j < 8; j++) {
        pa[j * 4] = pack_f16x2(o[j][0] * invA, o[j][1] * invA);
        pb[j * 4] = pack_f16x2(o[j][2] * invB, o[j][3] * invB);
    }
}

// ============================================================
// Kernel 3: out projection  out = ctx @ w_out + b_out  (fp16 core)
// ============================================================
__global__ __launch_bounds__(256, 2) void out_gemm(const float* __restrict__ bias,
                                                   float* __restrict__ out) {
    float acc[2][8][4];
#pragma unroll
    for (int i = 0; i < 2; i++)
#pragma unroll
        for (int j = 0; j < 8; j++)
#pragma unroll
            for (int r = 0; r < 4; r++) acc[i][j][r] = 0.f;

    gemm_core_h(g_ctxh, g_woutTh, acc);

    const int tid = threadIdx.x, lane = tid & 31, warp = tid >> 5;
    const int wm = warp >> 1, wn = warp & 1;
    const int n0 = blockIdx.x * 128 + wn * 64 + 2 * (lane & 3);
#pragma unroll
    for (int i = 0; i < 2; i++)
#pragma unroll
        for (int li = 0; li < 2; li++) {
            const int m = blockIdx.y * 128 + wm * 32 + i * 16 + li * 8 + (lane >> 2);
            float* op = out + (size_t)m * 768 + n0;
#pragma unroll
            for (int j = 0; j < 8; j++) {
                float2 bb = *(const float2*)(bias + n0 + j * 8);
                *(float2*)(op + j * 8) =
                    make_float2(acc[i][j][li * 2] + bb.x, acc[i][j][li * 2 + 1] + bb.y);
            }
        }
}

// ============================================================
extern "C" void kernel_launch(void* const* d_in, const int* in_sizes, int n_in,
                              void* d_out, int out_size) {
    const float* x     = (const float*)d_in[0];
    const float* w_qkv = (const float*)d_in[1];
    const float* w_out = (const float*)d_in[2];
    const float* b_out = (const float*)d_in[3];
    float* out = (float*)d_out;

    cudaFuncSetAttribute(qkv_gemm, cudaFuncAttributeMaxDynamicSharedMemorySize, 65536);
    cudaFuncSetAttribute(out_gemm, cudaFuncAttributeMaxDynamicSharedMemorySize, 65536);
    cudaFuncSetAttribute(attn_kernel, cudaFuncAttributeMaxDynamicSharedMemorySize, 65536);

    cvt_x_h<<<M_ * C_ / 2048, 256>>>(x);
    cvt_transpose_h<2304><<<dim3(2304 / 32, 768 / 32), dim3(32, 8)>>>(w_qkv);
    cvt_transpose_h<768><<<dim3(768 / 32, 768 / 32), dim3(32, 8)>>>(w_out);
    qkv_gemm<<<dim3(2304 / 128, M_ / 128), 256, 65536>>>();
    attn_kernel<<<dim3(N_ / 128, BH_), 256, 65536>>>();
    out_gemm<<<dim3(768 / 128, M_ / 128), 256, 65536>>>(b_out, out);
}